// round 13
// baseline (speedup 1.0000x reference)
#include <cuda_runtime.h>
#include <cuda_bf16.h>
#include <math.h>
#include <stdint.h>

#define B_    2
#define S_    2048
#define H_    16
#define D_    64
#define HID   1024
#define QKV_  1024
#define M_TOK 4096
#define N_QKV 3072
#define SCALE 0.125f

typedef unsigned long long u64;
typedef __nv_bfloat16 bf16;

// ---------------- helpers ----------------------------------------------------
__device__ __forceinline__ uint32_t pkbf(bf16 x, bf16 y) {
    __nv_bfloat162 t; t.x = x; t.y = y;
    return *(uint32_t*)&t;
}
__device__ __forceinline__ uint32_t splitp(float x, float y, uint32_t& lo) {
    bf16 hx = __float2bfloat16(x), hy = __float2bfloat16(y);
    bf16 lx = __float2bfloat16(x - __bfloat162float(hx));
    bf16 ly = __float2bfloat16(y - __bfloat162float(hy));
    lo = pkbf(lx, ly);
    return pkbf(hx, hy);
}
__device__ __forceinline__ void mma16816(float* d,
    uint32_t a0, uint32_t a1, uint32_t a2, uint32_t a3, uint32_t b0, uint32_t b1) {
    asm volatile(
        "mma.sync.aligned.m16n8k16.row.col.f32.bf16.bf16.f32 "
        "{%0,%1,%2,%3},{%4,%5,%6,%7},{%8,%9},{%0,%1,%2,%3};"
        : "+f"(d[0]), "+f"(d[1]), "+f"(d[2]), "+f"(d[3])
        : "r"(a0), "r"(a1), "r"(a2), "r"(a3), "r"(b0), "r"(b1));
}
__device__ __forceinline__ void mmas8(int* d, const uint32_t* a,
                                      uint32_t b0, uint32_t b1) {
    asm volatile(
        "mma.sync.aligned.m16n8k32.row.col.s32.s8.s8.s32 "
        "{%0,%1,%2,%3},{%4,%5,%6,%7},{%8,%9},{%0,%1,%2,%3};"
        : "+r"(d[0]), "+r"(d[1]), "+r"(d[2]), "+r"(d[3])
        : "r"(a[0]), "r"(a[1]), "r"(a[2]), "r"(a[3]), "r"(b0), "r"(b1));
}
__device__ __forceinline__ void ldsm4(uint32_t* r, uint32_t addr) {
    asm volatile("ldmatrix.sync.aligned.m8n8.x4.shared.b16 {%0,%1,%2,%3},[%4];"
                 : "=r"(r[0]), "=r"(r[1]), "=r"(r[2]), "=r"(r[3]) : "r"(addr));
}
__device__ __forceinline__ uint32_t smem_u32(const void* p) {
    uint32_t a;
    asm("{ .reg .u64 t; cvta.to.shared.u64 t, %1; cvt.u32.u64 %0, t; }" : "=r"(a) : "l"(p));
    return a;
}
__device__ __forceinline__ void bulkcp(uint32_t dst, const void* src,
                                       uint32_t bytes, uint32_t mbar) {
    asm volatile(
        "cp.async.bulk.shared::cluster.global.mbarrier::complete_tx::bytes "
        "[%0], [%1], %2, [%3];"
        :: "r"(dst), "l"(src), "r"(bytes), "r"(mbar) : "memory");
}
#define MBAR_INIT(a, c) \
    asm volatile("mbarrier.init.shared.b64 [%0], %1;" :: "r"(a), "r"(c) : "memory")
#define MBAR_EXPECT(a, bytes) \
    asm volatile("mbarrier.arrive.expect_tx.shared.b64 _, [%0], %1;" \
                 :: "r"(a), "r"(bytes) : "memory")
#define MBAR_ARRIVE(a) \
    asm volatile("mbarrier.arrive.shared.b64 _, [%0];" :: "r"(a) : "memory")
#define MBAR_WAIT(a, ph) do {                                                  \
    uint32_t _m = (a); uint32_t _p = (ph); uint32_t _done;                     \
    asm volatile("{ .reg .pred p; mbarrier.try_wait.parity.acquire.cta.shared::cta.b64 p, [%1], %2;" \
                 " selp.b32 %0,1,0,p; }" : "=r"(_done) : "r"(_m), "r"(_p) : "memory"); \
    if (!_done) {                                                              \
        asm volatile("{ .reg .pred P1; WL_%=:"                                 \
                     " mbarrier.try_wait.parity.acquire.cta.shared::cta.b64 P1, [%0], %1, 0x989680;" \
                     " @P1 bra.uni WD_%=; bra.uni WL_%=; WD_%=: }"             \
                     :: "r"(_m), "r"(_p) : "memory");                          \
    }                                                                          \
} while (0)

// ---------------- layout constants -------------------------------------------
#define AQLD 72
#define KPIECE (128 * AQLD)          // bf16 K tiles for attention (unchanged)
#define KSUB (64 * AQLD)
#define VP2 (64 * AQLD)
// int8 quant tiles: payload 64 B/row, stride 80 B
#define APC_B (128 * 80)             // A piece: 128 rows = 10240 B
#define BPC_B (64 * 80)              // B piece:  64 rows =  5120 B
#define QSZ(R, C) ((size_t)(R) * (C) * 5 / 4)

// ---------------- scratch ----------------------------------------------------
__device__ float g_qkv[(size_t)M_TOK * N_QKV];
__device__ float g_att[(size_t)M_TOK * QKV_];
__device__ signed char g_x1[QSZ(M_TOK, HID)],   g_x0[QSZ(M_TOK, HID)];
__device__ signed char g_wq1[QSZ(N_QKV, HID)],  g_wq0[QSZ(N_QKV, HID)];
__device__ signed char g_wo1[QSZ(HID, QKV_)],   g_wo0[QSZ(HID, QKV_)];
__device__ signed char g_at1[QSZ(M_TOK, QKV_)], g_at0[QSZ(M_TOK, QKV_)];
__device__ float g_sx[M_TOK], g_swq[N_QKV], g_swo[HID], g_sat[M_TOK];
__device__ bf16 g_kh[(size_t)512 * KPIECE], g_kl[(size_t)512 * KPIECE];
__device__ bf16 g_vh[(size_t)32 * 32 * VP2], g_vl[(size_t)32 * 32 * VP2];

// ---------------------------------------------------------------------------
// quant pre-pass: per-row 2-slice int8 (C must be 1024)
// ---------------------------------------------------------------------------
__global__ __launch_bounds__(128) void quant_rows(
    const float* __restrict__ src, signed char* __restrict__ q1,
    signed char* __restrict__ q0, float* __restrict__ scale, int prows)
{
    const int r = blockIdx.x;
    const int tid = threadIdx.x;
    const int c = tid * 8;
    const float* row = src + (size_t)r * 1024;
    float4 v0 = *(const float4*)(row + c);
    float4 v1 = *(const float4*)(row + c + 4);
    float vs[8] = {v0.x, v0.y, v0.z, v0.w, v1.x, v1.y, v1.z, v1.w};
    float mv = 0.f;
#pragma unroll
    for (int j = 0; j < 8; j++) mv = fmaxf(mv, fabsf(vs[j]));
    __shared__ float red[4];
#pragma unroll
    for (int o = 16; o > 0; o >>= 1)
        mv = fmaxf(mv, __shfl_xor_sync(0xffffffffu, mv, o));
    if ((tid & 31) == 0) red[tid >> 5] = mv;
    __syncthreads();
    float maxv = fmaxf(fmaxf(red[0], red[1]), fmaxf(red[2], red[3]));
    maxv = fmaxf(maxv, 1e-30f);
    if (tid == 0) scale[r] = maxv * (1.f / 16128.f);
    const float inv = 16128.f / maxv;
    signed char b1[8], b0[8];
#pragma unroll
    for (int j = 0; j < 8; j++) {
        float q = vs[j] * inv;
        int i1 = __float2int_rn(q * (1.f / 128.f));
        int i0 = __float2int_rn(q - 128.f * (float)i1);
        b1[j] = (signed char)i1;
        b0[j] = (signed char)i0;
    }
    const size_t piece = (size_t)((r / prows) * 16 + (c >> 6));
    const size_t off = piece * (size_t)(prows * 80)
                     + (size_t)(r % prows) * 80 + (c & 63);
    *(u64*)(q1 + off) = *(u64*)b1;
    *(u64*)(q0 + off) = *(u64*)b0;
}

// ---------------------------------------------------------------------------
// V transpose+split (unchanged from round 12, passing)
// ---------------------------------------------------------------------------
__global__ __launch_bounds__(256) void split_vt(
    const float* __restrict__ qkv, bf16* __restrict__ vh, bf16* __restrict__ vl)
{
    __shared__ float T[64][65];
    const int st = blockIdx.x;
    const int bh = blockIdx.y;
    const int b = bh >> 4, h = bh & 15;
    const int s0 = st * 64;
    const int tid = threadIdx.x;
    {
        const int sl = tid >> 2;
        const int cq = tid & 3;
        const float* src = qkv + ((size_t)(b * S_ + s0 + sl)) * N_QKV
                         + 2 * QKV_ + h * D_ + cq * 16;
#pragma unroll
        for (int j = 0; j < 4; j++) {
            float4 v = *(const float4*)(src + j * 4);
            T[cq * 16 + j * 4 + 0][sl] = v.x;
            T[cq * 16 + j * 4 + 1][sl] = v.y;
            T[cq * 16 + j * 4 + 2][sl] = v.z;
            T[cq * 16 + j * 4 + 3][sl] = v.w;
        }
    }
    __syncthreads();
    const int d = tid >> 2;
    const int sq = tid & 3;
    uint32_t hh[8], ll[8];
#pragma unroll
    for (int k = 0; k < 8; k++)
        hh[k] = splitp(T[d][sq * 16 + 2 * k], T[d][sq * 16 + 2 * k + 1], ll[k]);
    const size_t dst = (size_t)(bh * 32 + st) * VP2 + (size_t)d * AQLD + sq * 16;
    *(uint4*)(vh + dst)     = make_uint4(hh[0], hh[1], hh[2], hh[3]);
    *(uint4*)(vh + dst + 8) = make_uint4(hh[4], hh[5], hh[6], hh[7]);
    *(uint4*)(vl + dst)     = make_uint4(ll[0], ll[1], ll[2], ll[3]);
    *(uint4*)(vl + dst + 8) = make_uint4(ll[4], ll[5], ll[6], ll[7]);
}

// ---------------------------------------------------------------------------
// int8 2-slice NT GEMM: C = sa*sb*(A1B1*16384 + (A1B0+A0B1)*128) + bias
// CTA 128x64, 8 warps (warp tile 64x16), k-chunk 64, bulk-copy pipeline.
// ---------------------------------------------------------------------------
#define STG 30720                     // A1+A0 (10240 ea) + B1+B0 (5120 ea)
#define GEMM_SMEM (2 * STG + 32)

__global__ __launch_bounds__(256, 2) void gemm_s8(
    const signed char* __restrict__ A1, const signed char* __restrict__ A0,
    const signed char* __restrict__ B1, const signed char* __restrict__ B0,
    const float* __restrict__ sa, const float* __restrict__ sbv,
    const float* __restrict__ bias, float* __restrict__ C,
    bf16* __restrict__ kh, bf16* __restrict__ kl,
    int M, int N, int K, int kmode)
{
    extern __shared__ char smem[];
    const uint32_t sb = smem_u32(smem);
    const uint32_t dbar = sb + 2 * STG;
    const uint32_t fbar = dbar + 16;

    const int tid = threadIdx.x;
    const int wid = tid >> 5;
    const int lid = tid & 31;
    const int g   = lid >> 2;
    const int tg  = lid & 3;
    const int wm  = (wid & 1) * 64;
    const int wn  = (wid >> 1) * 16;
    const int bm  = blockIdx.y * 128;
    const int bn  = blockIdx.x * 64;

    const int kp = K >> 6;   // 64-elem k pieces
    const signed char* pA1 = A1 + (size_t)blockIdx.y * kp * APC_B;
    const signed char* pA0 = A0 + (size_t)blockIdx.y * kp * APC_B;
    const signed char* pB1 = B1 + (size_t)blockIdx.x * kp * BPC_B;
    const signed char* pB0 = B0 + (size_t)blockIdx.x * kp * BPC_B;

    if (tid == 0) {
        MBAR_INIT(dbar, 1);
        MBAR_INIT(dbar + 8, 1);
        MBAR_INIT(fbar, 8);
        MBAR_INIT(fbar + 8, 8);
    }
    __syncthreads();

    auto issue = [&](int buf, int c) {
        const uint32_t mb = dbar + buf * 8;
        const uint32_t d  = sb + buf * STG;
        MBAR_EXPECT(mb, STG);
        bulkcp(d,                 pA1 + (size_t)c * APC_B, APC_B, mb);
        bulkcp(d + APC_B,         pA0 + (size_t)c * APC_B, APC_B, mb);
        bulkcp(d + 2 * APC_B,     pB1 + (size_t)c * BPC_B, BPC_B, mb);
        bulkcp(d + 2 * APC_B + BPC_B, pB0 + (size_t)c * BPC_B, BPC_B, mb);
    };

    if (tid == 0) { issue(0, 0); issue(1, 1); }

    const uint32_t aLane = (uint32_t)(lid & 15) * 80 + ((lid >> 4) << 4);
    const uint32_t bAddr = (uint32_t)(wn + (lid & 15)) * 80 + ((lid >> 4) << 4);

    int acc1[4][2][4], acc2[4][2][4];
#pragma unroll
    for (int mi = 0; mi < 4; mi++)
#pragma unroll
        for (int ni = 0; ni < 2; ni++)
#pragma unroll
            for (int r = 0; r < 4; r++) { acc1[mi][ni][r] = 0; acc2[mi][ni][r] = 0; }

    int dph0 = 0, dph1 = 0, fph0 = 0, fph1 = 0;
    for (int c = 0; c < kp; c++) {
        const int buf = c & 1;
        if (buf == 0) { MBAR_WAIT(dbar, dph0); dph0 ^= 1; }
        else          { MBAR_WAIT(dbar + 8, dph1); dph1 ^= 1; }

        const uint32_t sA1 = sb + buf * STG;
        const uint32_t sA0 = sA1 + APC_B;
        const uint32_t sB1 = sA1 + 2 * APC_B;
        const uint32_t sB0 = sB1 + BPC_B;

#pragma unroll
        for (int k2 = 0; k2 < 2; k2++) {
            const uint32_t kOff = k2 * 32;
            uint32_t b1f[4], b0f[4];
            ldsm4(b1f, sB1 + bAddr + kOff);
            ldsm4(b0f, sB0 + bAddr + kOff);
#pragma unroll
            for (int mi = 0; mi < 4; mi++) {
                const uint32_t rOff = (uint32_t)(wm + mi * 16) * 80 + aLane + kOff;
                uint32_t a1[4], a0[4];
                ldsm4(a1, sA1 + rOff);
                ldsm4(a0, sA0 + rOff);
#pragma unroll
                for (int ni = 0; ni < 2; ni++) {
                    mmas8(acc1[mi][ni], a1, b1f[ni], b1f[ni + 2]);
                    mmas8(acc2[mi][ni], a1, b0f[ni], b0f[ni + 2]);
                    mmas8(acc2[mi][ni], a0, b1f[ni], b1f[ni + 2]);
                }
            }
        }

        if (lid == 0) MBAR_ARRIVE(fbar + buf * 8);
        if (tid == 0 && c + 2 < kp) {
            if (buf == 0) { MBAR_WAIT(fbar, fph0); fph0 ^= 1; }
            else          { MBAR_WAIT(fbar + 8, fph1); fph1 ^= 1; }
            issue(buf, c + 2);
        }
    }

    const bool ksplit = kmode && (bn >= QKV_) && (bn < 2 * QKV_);
#pragma unroll
    for (int ni = 0; ni < 2; ni++) {
        const int col = bn + wn + ni * 8 + tg * 2;
        const float sb0 = sbv[col], sb1 = sbv[col + 1];
        const float bx = bias[col], by = bias[col + 1];
#pragma unroll
        for (int mi = 0; mi < 4; mi++) {
            const int row = bm + wm + mi * 16 + g;
            const float sa0 = sa[row], sa1v = sa[row + 8];
            float v0 = fmaf((float)acc1[mi][ni][0], 16384.f,
                            (float)acc2[mi][ni][0] * 128.f) * sa0 * sb0 + bx;
            float v1 = fmaf((float)acc1[mi][ni][1], 16384.f,
                            (float)acc2[mi][ni][1] * 128.f) * sa0 * sb1 + by;
            float v2 = fmaf((float)acc1[mi][ni][2], 16384.f,
                            (float)acc2[mi][ni][2] * 128.f) * sa1v * sb0 + bx;
            float v3 = fmaf((float)acc1[mi][ni][3], 16384.f,
                            (float)acc2[mi][ni][3] * 128.f) * sa1v * sb1 + by;
            if (ksplit) {
                const int colq = col - QKV_;
                const int hh = colq >> 6, dd = colq & 63;
                uint32_t lo0, lo1;
                uint32_t hi0 = splitp(v0, v1, lo0);
                uint32_t hi1 = splitp(v2, v3, lo1);
#pragma unroll
                for (int rr = 0; rr < 2; rr++) {
                    const int r2 = row + rr * 8;
                    const size_t dst =
                        (size_t)((((r2 >> 11) << 4) + hh) * 16 + ((r2 >> 7) & 15)) * KPIECE
                        + (size_t)(r2 & 127) * AQLD + dd;
                    *(uint32_t*)&kh[dst] = rr ? hi1 : hi0;
                    *(uint32_t*)&kl[dst] = rr ? lo1 : lo0;
                }
            } else {
                *(float2*)&C[(size_t)row * N + col]       = make_float2(v0, v1);
                *(float2*)&C[(size_t)(row + 8) * N + col] = make_float2(v2, v3);
            }
        }
    }
}

// ---------------------------------------------------------------------------
// Tensor-core flash attention (round-12, passing) — epilogue now fp32 g_att
// ---------------------------------------------------------------------------
#define QT_B (128 * AQLD * 2)
#define KT2_B (64 * AQLD * 2)
#define OFF_QH 0
#define OFF_QL QT_B
#define OFF_K0 (2 * QT_B)
#define OFF_V0 (2 * QT_B + 2 * 2 * KT2_B)
#define ATT_MB (OFF_V0 + 2 * 2 * KT2_B)
#define ATT_SMEM (ATT_MB + 32)

__global__ __launch_bounds__(256, 2) void attn_tc(
    const float* __restrict__ qkv,
    const bf16* __restrict__ kh_g, const bf16* __restrict__ kl_g,
    const bf16* __restrict__ vh_g, const bf16* __restrict__ vl_g,
    float* __restrict__ outp)
{
    extern __shared__ char smc[];
    const uint32_t sb = smem_u32(smc);
    const uint32_t dbar = sb + ATT_MB;
    const uint32_t fbar = dbar + 16;
    bf16* Qh = (bf16*)(smc + OFF_QH);
    bf16* Ql = (bf16*)(smc + OFF_QL);

    const int tid = threadIdx.x;
    const int wid = tid >> 5;
    const int lid = tid & 31;
    const int g   = lid >> 2;
    const int tg  = lid & 3;
    const int qt  = blockIdx.x;
    const int bhx = blockIdx.y;
    const int b   = bhx >> 4;
    const int q0  = qt * 128;
    const size_t tok_base = (size_t)b * S_;
    const int hcol = (bhx & 15) * D_;
    const int wrow = wid * 16;

    if (tid == 0) {
        MBAR_INIT(dbar, 1);
        MBAR_INIT(dbar + 8, 1);
        MBAR_INIT(fbar, 8);
        MBAR_INIT(fbar + 8, 8);
    }

    {
        const int lr  = tid >> 1;
        const int lch = (tid & 1) * 32;
        const float* qp = qkv + (tok_base + q0 + lr) * (size_t)N_QKV + hcol + lch;
        const int base = lr * AQLD + lch;
#pragma unroll
        for (int j = 0; j < 8; j++) {
            float4 v = *(const float4*)(qp + j * 4);
            v.x *= SCALE; v.y *= SCALE; v.z *= SCALE; v.w *= SCALE;
            uint32_t lo0, lo1;
            uint32_t hi0 = splitp(v.x, v.y, lo0);
            uint32_t hi1 = splitp(v.z, v.w, lo1);
            *(uint32_t*)&Qh[base + j * 4]     = hi0;
            *(uint32_t*)&Qh[base + j * 4 + 2] = hi1;
            *(uint32_t*)&Ql[base + j * 4]     = lo0;
            *(uint32_t*)&Ql[base + j * 4 + 2] = lo1;
        }
    }
    __syncthreads();

    const bf16* pKh = kh_g + (size_t)bhx * 16 * KPIECE;
    const bf16* pKl = kl_g + (size_t)bhx * 16 * KPIECE;
    const bf16* pVh = vh_g + (size_t)bhx * 32 * VP2;
    const bf16* pVl = vl_g + (size_t)bhx * 32 * VP2;

    auto issue_kv = [&](int buf, int kt) {
        const uint32_t mb  = dbar + buf * 8;
        const uint32_t dkb = sb + OFF_K0 + buf * (2 * KT2_B);
        const uint32_t dvb = sb + OFF_V0 + buf * (2 * KT2_B);
        MBAR_EXPECT(mb, 4 * KT2_B);
        bulkcp(dkb,         pKh + (size_t)kt * KSUB, KT2_B, mb);
        bulkcp(dkb + KT2_B, pKl + (size_t)kt * KSUB, KT2_B, mb);
        bulkcp(dvb,         pVh + (size_t)kt * VP2,  KT2_B, mb);
        bulkcp(dvb + KT2_B, pVl + (size_t)kt * VP2,  KT2_B, mb);
    };

    if (tid == 0) { issue_kv(0, 0); issue_kv(1, 1); }

    const uint32_t qLane = (uint32_t)((wrow + (lid & 15)) * AQLD + ((lid >> 4) << 3)) * 2;
    const uint32_t rLane = (uint32_t)lid * 144;

    float acc_o[8][4];
#pragma unroll
    for (int dt = 0; dt < 8; dt++)
#pragma unroll
        for (int r = 0; r < 4; r++) acc_o[dt][r] = 0.f;
    float m0 = -INFINITY, m1 = -INFINITY, l0 = 0.f, l1 = 0.f;

    int dph0 = 0, dph1 = 0, fph0 = 0, fph1 = 0;
    const int nkt = S_ / 64;
    for (int kt = 0; kt < nkt; kt++) {
        const int buf = kt & 1;
        if (buf == 0) { MBAR_WAIT(dbar, dph0); dph0 ^= 1; }
        else          { MBAR_WAIT(dbar + 8, dph1); dph1 ^= 1; }

        const uint32_t sKH = sb + OFF_K0 + buf * (2 * KT2_B);
        const uint32_t sKL = sKH + KT2_B;
        const uint32_t sVH = sb + OFF_V0 + buf * (2 * KT2_B);
        const uint32_t sVL = sVH + KT2_B;

        float accs[8][4];
#pragma unroll
        for (int nt = 0; nt < 8; nt++)
#pragma unroll
            for (int r = 0; r < 4; r++) accs[nt][r] = 0.f;

#pragma unroll
        for (int ks = 0; ks < 4; ks++) {
            const uint32_t kOff = ks * 32;
            uint32_t ah[4], al[4];
            ldsm4(ah, sb + OFF_QH + qLane + kOff);
            ldsm4(al, sb + OFF_QL + qLane + kOff);
            uint32_t kh0[2][4], kh1[2][4], kl0[2][4], kl1[2][4];
#pragma unroll
            for (int n2 = 0; n2 < 2; n2++) {
                const uint32_t kAddr = n2 * (32 * 144) + rLane + kOff;
                ldsm4(kh0[n2], sKH + kAddr);
                ldsm4(kh1[n2], sKH + kAddr + 16);
                ldsm4(kl0[n2], sKL + kAddr);
                ldsm4(kl1[n2], sKL + kAddr + 16);
            }
#pragma unroll
            for (int n2 = 0; n2 < 2; n2++)
#pragma unroll
                for (int q = 0; q < 4; q++)
                    mma16816(accs[n2 * 4 + q], ah[0], ah[1], ah[2], ah[3],
                             kh0[n2][q], kh1[n2][q]);
#pragma unroll
            for (int n2 = 0; n2 < 2; n2++)
#pragma unroll
                for (int q = 0; q < 4; q++)
                    mma16816(accs[n2 * 4 + q], ah[0], ah[1], ah[2], ah[3],
                             kl0[n2][q], kl1[n2][q]);
#pragma unroll
            for (int n2 = 0; n2 < 2; n2++)
#pragma unroll
                for (int q = 0; q < 4; q++)
                    mma16816(accs[n2 * 4 + q], al[0], al[1], al[2], al[3],
                             kh0[n2][q], kh1[n2][q]);
        }

        float nm0 = m0, nm1 = m1;
#pragma unroll
        for (int nt = 0; nt < 8; nt++) {
            nm0 = fmaxf(nm0, fmaxf(accs[nt][0], accs[nt][1]));
            nm1 = fmaxf(nm1, fmaxf(accs[nt][2], accs[nt][3]));
        }
        nm0 = fmaxf(nm0, __shfl_xor_sync(0xffffffffu, nm0, 1));
        nm0 = fmaxf(nm0, __shfl_xor_sync(0xffffffffu, nm0, 2));
        nm1 = fmaxf(nm1, __shfl_xor_sync(0xffffffffu, nm1, 1));
        nm1 = fmaxf(nm1, __shfl_xor_sync(0xffffffffu, nm1, 2));
        const float corr0 = __expf(m0 - nm0);
        const float corr1 = __expf(m1 - nm1);
        float rs0 = 0.f, rs1 = 0.f;
#pragma unroll
        for (int nt = 0; nt < 8; nt++) {
            accs[nt][0] = __expf(accs[nt][0] - nm0);
            accs[nt][1] = __expf(accs[nt][1] - nm0);
            accs[nt][2] = __expf(accs[nt][2] - nm1);
            accs[nt][3] = __expf(accs[nt][3] - nm1);
            rs0 += accs[nt][0] + accs[nt][1];
            rs1 += accs[nt][2] + accs[nt][3];
        }
        rs0 += __shfl_xor_sync(0xffffffffu, rs0, 1);
        rs0 += __shfl_xor_sync(0xffffffffu, rs0, 2);
        rs1 += __shfl_xor_sync(0xffffffffu, rs1, 1);
        rs1 += __shfl_xor_sync(0xffffffffu, rs1, 2);
        l0 = l0 * corr0 + rs0;
        l1 = l1 * corr1 + rs1;
        m0 = nm0; m1 = nm1;
#pragma unroll
        for (int dt = 0; dt < 8; dt++) {
            acc_o[dt][0] *= corr0;
            acc_o[dt][1] *= corr0;
            acc_o[dt][2] *= corr1;
            acc_o[dt][3] *= corr1;
        }

#pragma unroll
        for (int kc = 0; kc < 4; kc++) {
            uint32_t pah[4], pal[4];
            pah[0] = splitp(accs[2 * kc][0],     accs[2 * kc][1],     pal[0]);
            pah[1] = splitp(accs[2 * kc][2],     accs[2 * kc][3],     pal[1]);
            pah[2] = splitp(accs[2 * kc + 1][0], accs[2 * kc + 1][1], pal[2]);
            pah[3] = splitp(accs[2 * kc + 1][2], accs[2 * kc + 1][3], pal[3]);
            const uint32_t vOff = kc * 32;
            uint32_t vh0[2][4], vh1[2][4], vl0[2][4], vl1[2][4];
#pragma unroll
            for (int d2 = 0; d2 < 2; d2++) {
                const uint32_t vAddr = d2 * (32 * 144) + rLane + vOff;
                ldsm4(vh0[d2], sVH + vAddr);
                ldsm4(vh1[d2], sVH + vAddr + 16);
                ldsm4(vl0[d2], sVL + vAddr);
                ldsm4(vl1[d2], sVL + vAddr + 16);
            }
#pragma unroll
            for (int d2 = 0; d2 < 2; d2++)
#pragma unroll
                for (int q = 0; q < 4; q++)
                    mma16816(acc_o[d2 * 4 + q], pah[0], pah[1], pah[2], pah[3],
                             vh0[d2][q], vh1[d2][q]);
#pragma unroll
            for (int d2 = 0; d2 < 2; d2++)
#pragma unroll
                for (int q = 0; q < 4; q++)
                    mma16816(acc_o[d2 * 4 + q], pah[0], pah[1], pah[2], pah[3],
                             vl0[d2][q], vl1[d2][q]);
#pragma unroll
            for (int d2 = 0; d2 < 2; d2++)
#pragma unroll
                for (int q = 0; q < 4; q++)
                    mma16816(acc_o[d2 * 4 + q], pal[0], pal[1], pal[2], pal[3],
                             vh0[d2][q], vh1[d2][q]);
        }

        if (lid == 0) MBAR_ARRIVE(fbar + buf * 8);
        if (tid == 0 && kt + 2 < nkt) {
            if (buf == 0) { MBAR_WAIT(fbar, fph0); fph0 ^= 1; }
            else          { MBAR_WAIT(fbar + 8, fph1); fph1 ^= 1; }
            issue_kv(buf, kt + 2);
        }
    }

    // fp32 epilogue (row-major g_att)
    const float inv0 = 1.f / l0;
    const float inv1 = 1.f / l1;
    const size_t row0 = tok_base + q0 + wrow + g;
    const size_t row1 = row0 + 8;
#pragma unroll
    for (int dt = 0; dt < 8; dt++) {
        const int col = hcol + dt * 8 + tg * 2;
        *(float2*)&outp[row0 * QKV_ + col] =
            make_float2(acc_o[dt][0] * inv0, acc_o[dt][1] * inv0);
        *(float2*)&outp[row1 * QKV_ + col] =
            make_float2(acc_o[dt][2] * inv1, acc_o[dt][3] * inv1);
    }
}

// ---------------------------------------------------------------------------
extern "C" void kernel_launch(void* const* d_in, const int* in_sizes, int n_in,
                              void* d_out, int out_size)
{
    const float* x     = (const float*)d_in[0];
    const float* w_qkv = (const float*)d_in[1];
    const float* b_qkv = (const float*)d_in[2];
    const float* w_o   = (const float*)d_in[3];
    const float* b_o   = (const float*)d_in[4];
    float* out = (float*)d_out;

    float *p_qkv, *p_att, *p_sx, *p_swq, *p_swo, *p_sat;
    signed char *p_x1, *p_x0, *p_wq1, *p_wq0, *p_wo1, *p_wo0, *p_at1, *p_at0;
    bf16 *p_kh, *p_kl, *p_vh, *p_vl;
    cudaGetSymbolAddress((void**)&p_qkv, g_qkv);
    cudaGetSymbolAddress((void**)&p_att, g_att);
    cudaGetSymbolAddress((void**)&p_x1, g_x1);
    cudaGetSymbolAddress((void**)&p_x0, g_x0);
    cudaGetSymbolAddress((void**)&p_wq1, g_wq1);
    cudaGetSymbolAddress((void**)&p_wq0, g_wq0);
    cudaGetSymbolAddress((void**)&p_wo1, g_wo1);
    cudaGetSymbolAddress((void**)&p_wo0, g_wo0);
    cudaGetSymbolAddress((void**)&p_at1, g_at1);
    cudaGetSymbolAddress((void**)&p_at0, g_at0);
    cudaGetSymbolAddress((void**)&p_sx, g_sx);
    cudaGetSymbolAddress((void**)&p_swq, g_swq);
    cudaGetSymbolAddress((void**)&p_swo, g_swo);
    cudaGetSymbolAddress((void**)&p_sat, g_sat);
    cudaGetSymbolAddress((void**)&p_kh, g_kh);
    cudaGetSymbolAddress((void**)&p_kl, g_kl);
    cudaGetSymbolAddress((void**)&p_vh, g_vh);
    cudaGetSymbolAddress((void**)&p_vl, g_vl);

    cudaFuncSetAttribute(gemm_s8, cudaFuncAttributeMaxDynamicSharedMemorySize,
                         GEMM_SMEM);
    cudaFuncSetAttribute(attn_tc, cudaFuncAttributeMaxDynamicSharedMemorySize,
                         ATT_SMEM);

    // quantize inputs/weights
    quant_rows<<<M_TOK, 128>>>(x, p_x1, p_x0, p_sx, 128);
    quant_rows<<<N_QKV, 128>>>(w_qkv, p_wq1, p_wq0, p_swq, 64);
    quant_rows<<<HID, 128>>>(w_o, p_wo1, p_wo0, p_swo, 64);

    // 1) QKV projection (int8), K columns emitted as bf16 tiles
    {
        dim3 grid(N_QKV / 64, M_TOK / 128);
        gemm_s8<<<grid, 256, GEMM_SMEM>>>(p_x1, p_x0, p_wq1, p_wq0, p_sx, p_swq,
                                          b_qkv, p_qkv, p_kh, p_kl,
                                          M_TOK, N_QKV, HID, 1);
    }
    // V transpose+split
    {
        dim3 grid(S_ / 64, B_ * H_);
        split_vt<<<grid, 256>>>(p_qkv, p_vh, p_vl);
    }
    // 2) attention (bf16, fp32 output)
    {
        dim3 grid(S_ / 128, B_ * H_);
        attn_tc<<<grid, 256, ATT_SMEM>>>(p_qkv, p_kh, p_kl, p_vh, p_vl, p_att);
    }
    // quantize attention output, then 3) output projection (int8)
    quant_rows<<<M_TOK, 128>>>(p_att, p_at1, p_at0, p_sat, 128);
    {
        dim3 grid(QKV_ / 64, M_TOK / 128);
        gemm_s8<<<grid, 256, GEMM_SMEM>>>(p_at1, p_at0, p_wo1, p_wo0, p_sat, p_swo,
                                          b_o, out, nullptr, nullptr,
                                          M_TOK, QKV_, HID, 0);
    }
}

// round 14
// speedup vs baseline: 2.4538x; 2.4538x over previous
#include <cuda_runtime.h>
#include <cuda_fp16.h>
#include <math.h>
#include <stdint.h>

#define B_    2
#define S_    2048
#define H_    16
#define D_    64
#define HID   1024
#define QKV_  1024
#define M_TOK 4096
#define N_QKV 3072
#define SCALE 0.125f

typedef unsigned long long u64;
typedef __half f16;

// ---------------- helpers ----------------------------------------------------
__device__ __forceinline__ uint32_t packh(float x, float y) {
    __half2 h = __floats2half2_rn(x, y);
    return *(uint32_t*)&h;
}
// split pair into fp16 hi (returned) and fp16 lo (out)
__device__ __forceinline__ uint32_t splith(float x, float y, uint32_t& lo) {
    __half hx = __float2half_rn(x), hy = __float2half_rn(y);
    __half lx = __float2half_rn(x - __half2float(hx));
    __half ly = __float2half_rn(y - __half2float(hy));
    __half2 l2; l2.x = lx; l2.y = ly;
    __half2 h2; h2.x = hx; h2.y = hy;
    lo = *(uint32_t*)&l2;
    return *(uint32_t*)&h2;
}
__device__ __forceinline__ void mmah(float* d,
    uint32_t a0, uint32_t a1, uint32_t a2, uint32_t a3, uint32_t b0, uint32_t b1) {
    asm volatile(
        "mma.sync.aligned.m16n8k16.row.col.f32.f16.f16.f32 "
        "{%0,%1,%2,%3},{%4,%5,%6,%7},{%8,%9},{%0,%1,%2,%3};"
        : "+f"(d[0]), "+f"(d[1]), "+f"(d[2]), "+f"(d[3])
        : "r"(a0), "r"(a1), "r"(a2), "r"(a3), "r"(b0), "r"(b1));
}
__device__ __forceinline__ void ldsm4(uint32_t* r, uint32_t addr) {
    asm volatile("ldmatrix.sync.aligned.m8n8.x4.shared.b16 {%0,%1,%2,%3},[%4];"
                 : "=r"(r[0]), "=r"(r[1]), "=r"(r[2]), "=r"(r[3]) : "r"(addr));
}
__device__ __forceinline__ uint32_t smem_u32(const void* p) {
    uint32_t a;
    asm("{ .reg .u64 t; cvta.to.shared.u64 t, %1; cvt.u32.u64 %0, t; }" : "=r"(a) : "l"(p));
    return a;
}
__device__ __forceinline__ void bulkcp(uint32_t dst, const void* src,
                                       uint32_t bytes, uint32_t mbar) {
    asm volatile(
        "cp.async.bulk.shared::cluster.global.mbarrier::complete_tx::bytes "
        "[%0], [%1], %2, [%3];"
        :: "r"(dst), "l"(src), "r"(bytes), "r"(mbar) : "memory");
}
#define MBAR_INIT(a, c) \
    asm volatile("mbarrier.init.shared.b64 [%0], %1;" :: "r"(a), "r"(c) : "memory")
#define MBAR_EXPECT(a, bytes) \
    asm volatile("mbarrier.arrive.expect_tx.shared.b64 _, [%0], %1;" \
                 :: "r"(a), "r"(bytes) : "memory")
#define MBAR_ARRIVE(a) \
    asm volatile("mbarrier.arrive.shared.b64 _, [%0];" :: "r"(a) : "memory")
#define MBAR_WAIT(a, ph) do {                                                  \
    uint32_t _m = (a); uint32_t _p = (ph); uint32_t _done;                     \
    asm volatile("{ .reg .pred p; mbarrier.try_wait.parity.acquire.cta.shared::cta.b64 p, [%1], %2;" \
                 " selp.b32 %0,1,0,p; }" : "=r"(_done) : "r"(_m), "r"(_p) : "memory"); \
    if (!_done) {                                                              \
        asm volatile("{ .reg .pred P1; WL_%=:"                                 \
                     " mbarrier.try_wait.parity.acquire.cta.shared::cta.b64 P1, [%0], %1, 0x989680;" \
                     " @P1 bra.uni WD_%=; bra.uni WL_%=; WD_%=: }"             \
                     :: "r"(_m), "r"(_p) : "memory");                          \
    }                                                                          \
} while (0)

// ---------------- tiled layout constants -------------------------------------
#define GLD2 40
#define APIECE (128 * GLD2)
#define AQLD 72
#define KPIECE (128 * AQLD)
#define KSUB (64 * AQLD)
#define VP2 (64 * AQLD)

// ---------------- scratch ----------------------------------------------------
__device__ float g_qkv[(size_t)M_TOK * N_QKV];
__device__ f16 g_xh[(size_t)32 * 32 * APIECE];
__device__ f16 g_wqh[(size_t)24 * 32 * APIECE], g_wql[(size_t)24 * 32 * APIECE];
__device__ f16 g_woh[(size_t)8 * 32 * APIECE],  g_wol[(size_t)8 * 32 * APIECE];
__device__ f16 g_ath[(size_t)32 * 32 * APIECE];
__device__ f16 g_kh[(size_t)512 * KPIECE],      g_kl[(size_t)512 * KPIECE];
__device__ f16 g_vh[(size_t)32 * 32 * VP2],     g_vl[(size_t)32 * 32 * VP2];

// ---------------------------------------------------------------------------
// split pre-pass: fp32 row-major [R][C] -> tiled fp16 hi (+ optional lo)
// ---------------------------------------------------------------------------
__global__ __launch_bounds__(256) void split_tiled(
    const float* __restrict__ src, f16* __restrict__ h, f16* __restrict__ l, int C)
{
    const size_t e = ((size_t)blockIdx.x * 256 + threadIdx.x) * 8;
    const int r = (int)(e / C), c = (int)(e % C);
    float4 a = *(const float4*)(src + e);
    float4 b = *(const float4*)(src + e + 4);
    const size_t dst = ((size_t)((r >> 7) * (C >> 5) + (c >> 5))) * APIECE
                     + (size_t)(r & 127) * GLD2 + (c & 31);
    if (l) {
        uint32_t l0, l1, l2, l3;
        uint32_t h0 = splith(a.x, a.y, l0);
        uint32_t h1 = splith(a.z, a.w, l1);
        uint32_t h2 = splith(b.x, b.y, l2);
        uint32_t h3 = splith(b.z, b.w, l3);
        *(uint4*)(h + dst) = make_uint4(h0, h1, h2, h3);
        *(uint4*)(l + dst) = make_uint4(l0, l1, l2, l3);
    } else {
        uint32_t h0 = packh(a.x, a.y);
        uint32_t h1 = packh(a.z, a.w);
        uint32_t h2 = packh(b.x, b.y);
        uint32_t h3 = packh(b.z, b.w);
        *(uint4*)(h + dst) = make_uint4(h0, h1, h2, h3);
    }
}

// V transpose+split: [bh][st] pieces of [64 d][72] (64 s + pad), fp16 h+l
__global__ __launch_bounds__(256) void split_vt(
    const float* __restrict__ qkv, f16* __restrict__ vh, f16* __restrict__ vl)
{
    __shared__ float T[64][65];
    const int st = blockIdx.x;
    const int bh = blockIdx.y;
    const int b = bh >> 4, h = bh & 15;
    const int s0 = st * 64;
    const int tid = threadIdx.x;
    {
        const int sl = tid >> 2;
        const int cq = tid & 3;
        const float* src = qkv + ((size_t)(b * S_ + s0 + sl)) * N_QKV
                         + 2 * QKV_ + h * D_ + cq * 16;
#pragma unroll
        for (int j = 0; j < 4; j++) {
            float4 v = *(const float4*)(src + j * 4);
            T[cq * 16 + j * 4 + 0][sl] = v.x;
            T[cq * 16 + j * 4 + 1][sl] = v.y;
            T[cq * 16 + j * 4 + 2][sl] = v.z;
            T[cq * 16 + j * 4 + 3][sl] = v.w;
        }
    }
    __syncthreads();
    const int d = tid >> 2;
    const int sq = tid & 3;
    uint32_t hh[8], ll[8];
#pragma unroll
    for (int k = 0; k < 8; k++)
        hh[k] = splith(T[d][sq * 16 + 2 * k], T[d][sq * 16 + 2 * k + 1], ll[k]);
    const size_t dst = (size_t)(bh * 32 + st) * VP2 + (size_t)d * AQLD + sq * 16;
    *(uint4*)(vh + dst)     = make_uint4(hh[0], hh[1], hh[2], hh[3]);
    *(uint4*)(vh + dst + 8) = make_uint4(hh[4], hh[5], hh[6], hh[7]);
    *(uint4*)(vl + dst)     = make_uint4(ll[0], ll[1], ll[2], ll[3]);
    *(uint4*)(vl + dst + 8) = make_uint4(ll[4], ll[5], ll[6], ll[7]);
}

// ---------------------------------------------------------------------------
// fp16 NT GEMM (2-term): C = Ah*Bh^T + Ah*Bl^T + bias
// CTA 128x128, 8 warps (64x32), bulk-copy pipeline, barrier-free handoff.
// ---------------------------------------------------------------------------
#define GT_B (128 * GLD2 * 2)          // 10240
#define STG3 (3 * GT_B)                // Ah + Bh + Bl = 30720
#define GEMM_SMEM (2 * STG3 + 32)

__global__ __launch_bounds__(256, 2) void gemm_f16(
    const f16* __restrict__ Ah,
    const f16* __restrict__ Bh, const f16* __restrict__ Bl,
    const float* __restrict__ bias, float* __restrict__ C,
    f16* __restrict__ kh, f16* __restrict__ kl,
    int M, int N, int K, int kmode)
{
    extern __shared__ char smem[];
    const uint32_t sb = smem_u32(smem);
    const uint32_t dbar = sb + 2 * STG3;
    const uint32_t fbar = dbar + 16;

    const int tid = threadIdx.x;
    const int wid = tid >> 5;
    const int lid = tid & 31;
    const int g   = lid >> 2;
    const int tg  = lid & 3;
    const int wm  = (wid & 1) * 64;
    const int wn  = (wid >> 1) * 32;
    const int bm  = blockIdx.y * 128;
    const int bn  = blockIdx.x * 128;

    const int kp = K >> 5;
    const f16* pAh = Ah + (size_t)blockIdx.y * kp * APIECE;
    const f16* pBh = Bh + (size_t)blockIdx.x * kp * APIECE;
    const f16* pBl = Bl + (size_t)blockIdx.x * kp * APIECE;

    if (tid == 0) {
        MBAR_INIT(dbar, 1);
        MBAR_INIT(dbar + 8, 1);
        MBAR_INIT(fbar, 8);
        MBAR_INIT(fbar + 8, 8);
    }
    __syncthreads();

    auto issue = [&](int buf, int c) {
        const uint32_t mb = dbar + buf * 8;
        const uint32_t d  = sb + buf * STG3;
        MBAR_EXPECT(mb, STG3);
        bulkcp(d,            pAh + (size_t)c * APIECE, GT_B, mb);
        bulkcp(d + GT_B,     pBh + (size_t)c * APIECE, GT_B, mb);
        bulkcp(d + 2 * GT_B, pBl + (size_t)c * APIECE, GT_B, mb);
    };

    if (tid == 0) { issue(0, 0); issue(1, 1); }

    const uint32_t aLane = (uint32_t)((lid & 15) * GLD2 + ((lid >> 4) << 3)) * 2;
    const uint32_t bLane = (uint32_t)((wn + lid) * GLD2) * 2;

    float acc[4][4][4];
#pragma unroll
    for (int mi = 0; mi < 4; mi++)
#pragma unroll
        for (int ni = 0; ni < 4; ni++)
#pragma unroll
            for (int r = 0; r < 4; r++) acc[mi][ni][r] = 0.f;

    int dph0 = 0, dph1 = 0, fph0 = 0, fph1 = 0;
    for (int c = 0; c < kp; c++) {
        const int buf = c & 1;
        if (buf == 0) { MBAR_WAIT(dbar, dph0); dph0 ^= 1; }
        else          { MBAR_WAIT(dbar + 8, dph1); dph1 ^= 1; }

        const uint32_t sAH = sb + buf * STG3;
        const uint32_t sBH = sAH + GT_B;
        const uint32_t sBL = sAH + 2 * GT_B;

#pragma unroll
        for (int k2 = 0; k2 < 2; k2++) {
            const uint32_t kOff = k2 * 32;
            uint32_t bh0[4], bh1[4], bl0[4], bl1[4];
            ldsm4(bh0, sBH + bLane + kOff);
            ldsm4(bh1, sBH + bLane + kOff + 16);
            ldsm4(bl0, sBL + bLane + kOff);
            ldsm4(bl1, sBL + bLane + kOff + 16);
#pragma unroll
            for (int mi = 0; mi < 4; mi++) {
                const uint32_t rOff = (uint32_t)(wm + mi * 16) * 80 + aLane + kOff;
                uint32_t ah[4];
                ldsm4(ah, sAH + rOff);
#pragma unroll
                for (int ni = 0; ni < 4; ni++)
                    mmah(acc[mi][ni], ah[0], ah[1], ah[2], ah[3], bh0[ni], bh1[ni]);
#pragma unroll
                for (int ni = 0; ni < 4; ni++)
                    mmah(acc[mi][ni], ah[0], ah[1], ah[2], ah[3], bl0[ni], bl1[ni]);
            }
        }

        if (lid == 0) MBAR_ARRIVE(fbar + buf * 8);
        if (tid == 0 && c + 2 < kp) {
            if (buf == 0) { MBAR_WAIT(fbar, fph0); fph0 ^= 1; }
            else          { MBAR_WAIT(fbar + 8, fph1); fph1 ^= 1; }
            issue(buf, c + 2);
        }
    }

    const bool ksplit = kmode && (bn >= QKV_) && (bn < 2 * QKV_);
    if (ksplit) {
#pragma unroll
        for (int ni = 0; ni < 4; ni++) {
            const int col = bn + wn + ni * 8 + tg * 2;
            const float bx = bias[col], by = bias[col + 1];
            const int colq = col - QKV_;
            const int hh = colq >> 6, dd = colq & 63;
#pragma unroll
            for (int mi = 0; mi < 4; mi++) {
                const int row = bm + wm + mi * 16 + g;
                uint32_t lo0, lo1;
                uint32_t hi0 = splith(acc[mi][ni][0] + bx, acc[mi][ni][1] + by, lo0);
                uint32_t hi1 = splith(acc[mi][ni][2] + bx, acc[mi][ni][3] + by, lo1);
#pragma unroll
                for (int rr = 0; rr < 2; rr++) {
                    const int r2 = row + rr * 8;
                    const size_t dst =
                        (size_t)((((r2 >> 11) << 4) + hh) * 16 + ((r2 >> 7) & 15)) * KPIECE
                        + (size_t)(r2 & 127) * AQLD + dd;
                    *(uint32_t*)&kh[dst] = rr ? hi1 : hi0;
                    *(uint32_t*)&kl[dst] = rr ? lo1 : lo0;
                }
            }
        }
    } else {
#pragma unroll
        for (int ni = 0; ni < 4; ni++) {
            const int col = bn + wn + ni * 8 + tg * 2;
            const float bx = bias[col], by = bias[col + 1];
#pragma unroll
            for (int mi = 0; mi < 4; mi++) {
                const int row = bm + wm + mi * 16 + g;
                float2 w0, w1;
                w0.x = acc[mi][ni][0] + bx;
                w0.y = acc[mi][ni][1] + by;
                w1.x = acc[mi][ni][2] + bx;
                w1.y = acc[mi][ni][3] + by;
                *(float2*)&C[(size_t)row * N + col]       = w0;
                *(float2*)&C[(size_t)(row + 8) * N + col] = w1;
            }
        }
    }
}

// ---------------------------------------------------------------------------
// fp16 flash attention (2-term): KV tile 64, 2 CTA/SM, bulk-copy pipeline.
// Q high only; K h+l; V h+l; P high only.
// ---------------------------------------------------------------------------
#define QT_B (128 * AQLD * 2)       // 18432 (Qh only)
#define KT2_B (64 * AQLD * 2)       // 9216
#define OFF_QH 0
#define OFF_K0 QT_B
#define OFF_V0 (QT_B + 4 * KT2_B)
#define ATT_MB (OFF_V0 + 4 * KT2_B)
#define ATT_SMEM (ATT_MB + 32)      // 92192

__global__ __launch_bounds__(256, 2) void attn_tc(
    const float* __restrict__ qkv,
    const f16* __restrict__ kh_g, const f16* __restrict__ kl_g,
    const f16* __restrict__ vh_g, const f16* __restrict__ vl_g,
    f16* __restrict__ oh)
{
    extern __shared__ char smc[];
    const uint32_t sb = smem_u32(smc);
    const uint32_t dbar = sb + ATT_MB;
    const uint32_t fbar = dbar + 16;
    f16* Qh = (f16*)(smc + OFF_QH);

    const int tid = threadIdx.x;
    const int wid = tid >> 5;
    const int lid = tid & 31;
    const int g   = lid >> 2;
    const int tg  = lid & 3;
    const int qt  = blockIdx.x;
    const int bhx = blockIdx.y;
    const int b   = bhx >> 4;
    const int q0  = qt * 128;
    const size_t tok_base = (size_t)b * S_;
    const int hcol = (bhx & 15) * D_;
    const int wrow = wid * 16;

    if (tid == 0) {
        MBAR_INIT(dbar, 1);
        MBAR_INIT(dbar + 8, 1);
        MBAR_INIT(fbar, 8);
        MBAR_INIT(fbar + 8, 8);
    }

    // Q load: fp32 -> scaled fp16 high
    {
        const int lr  = tid >> 1;
        const int lch = (tid & 1) * 32;
        const float* qp = qkv + (tok_base + q0 + lr) * (size_t)N_QKV + hcol + lch;
        const int base = lr * AQLD + lch;
#pragma unroll
        for (int j = 0; j < 8; j++) {
            float4 v = *(const float4*)(qp + j * 4);
            *(uint32_t*)&Qh[base + j * 4]     = packh(v.x * SCALE, v.y * SCALE);
            *(uint32_t*)&Qh[base + j * 4 + 2] = packh(v.z * SCALE, v.w * SCALE);
        }
    }
    __syncthreads();

    const f16* pKh = kh_g + (size_t)bhx * 16 * KPIECE;
    const f16* pKl = kl_g + (size_t)bhx * 16 * KPIECE;
    const f16* pVh = vh_g + (size_t)bhx * 32 * VP2;
    const f16* pVl = vl_g + (size_t)bhx * 32 * VP2;

    auto issue_kv = [&](int buf, int kt) {
        const uint32_t mb  = dbar + buf * 8;
        const uint32_t dkb = sb + OFF_K0 + buf * (2 * KT2_B);
        const uint32_t dvb = sb + OFF_V0 + buf * (2 * KT2_B);
        MBAR_EXPECT(mb, 4 * KT2_B);
        bulkcp(dkb,         pKh + (size_t)kt * KSUB, KT2_B, mb);
        bulkcp(dkb + KT2_B, pKl + (size_t)kt * KSUB, KT2_B, mb);
        bulkcp(dvb,         pVh + (size_t)kt * VP2,  KT2_B, mb);
        bulkcp(dvb + KT2_B, pVl + (size_t)kt * VP2,  KT2_B, mb);
    };

    if (tid == 0) { issue_kv(0, 0); issue_kv(1, 1); }

    const uint32_t qLane = (uint32_t)((wrow + (lid & 15)) * AQLD + ((lid >> 4) << 3)) * 2;
    const uint32_t rLane = (uint32_t)lid * 144;

    float acc_o[8][4];
#pragma unroll
    for (int dt = 0; dt < 8; dt++)
#pragma unroll
        for (int r = 0; r < 4; r++) acc_o[dt][r] = 0.f;
    float m0 = -INFINITY, m1 = -INFINITY, l0 = 0.f, l1 = 0.f;

    int dph0 = 0, dph1 = 0, fph0 = 0, fph1 = 0;
    const int nkt = S_ / 64;
    for (int kt = 0; kt < nkt; kt++) {
        const int buf = kt & 1;
        if (buf == 0) { MBAR_WAIT(dbar, dph0); dph0 ^= 1; }
        else          { MBAR_WAIT(dbar + 8, dph1); dph1 ^= 1; }

        const uint32_t sKH = sb + OFF_K0 + buf * (2 * KT2_B);
        const uint32_t sKL = sKH + KT2_B;
        const uint32_t sVH = sb + OFF_V0 + buf * (2 * KT2_B);
        const uint32_t sVL = sVH + KT2_B;

        // ---- scores: qh·kh + qh·kl ----
        float accs[8][4];
#pragma unroll
        for (int nt = 0; nt < 8; nt++)
#pragma unroll
            for (int r = 0; r < 4; r++) accs[nt][r] = 0.f;

#pragma unroll
        for (int ks = 0; ks < 4; ks++) {
            const uint32_t kOff = ks * 32;
            uint32_t ah[4];
            ldsm4(ah, sb + OFF_QH + qLane + kOff);
            uint32_t kh0[2][4], kh1[2][4], kl0[2][4], kl1[2][4];
#pragma unroll
            for (int n2 = 0; n2 < 2; n2++) {
                const uint32_t kAddr = n2 * (32 * 144) + rLane + kOff;
                ldsm4(kh0[n2], sKH + kAddr);
                ldsm4(kh1[n2], sKH + kAddr + 16);
                ldsm4(kl0[n2], sKL + kAddr);
                ldsm4(kl1[n2], sKL + kAddr + 16);
            }
#pragma unroll
            for (int n2 = 0; n2 < 2; n2++)
#pragma unroll
                for (int q = 0; q < 4; q++)
                    mmah(accs[n2 * 4 + q], ah[0], ah[1], ah[2], ah[3],
                         kh0[n2][q], kh1[n2][q]);
#pragma unroll
            for (int n2 = 0; n2 < 2; n2++)
#pragma unroll
                for (int q = 0; q < 4; q++)
                    mmah(accs[n2 * 4 + q], ah[0], ah[1], ah[2], ah[3],
                         kl0[n2][q], kl1[n2][q]);
        }

        // ---- online softmax ----
        float nm0 = m0, nm1 = m1;
#pragma unroll
        for (int nt = 0; nt < 8; nt++) {
            nm0 = fmaxf(nm0, fmaxf(accs[nt][0], accs[nt][1]));
            nm1 = fmaxf(nm1, fmaxf(accs[nt][2], accs[nt][3]));
        }
        nm0 = fmaxf(nm0, __shfl_xor_sync(0xffffffffu, nm0, 1));
        nm0 = fmaxf(nm0, __shfl_xor_sync(0xffffffffu, nm0, 2));
        nm1 = fmaxf(nm1, __shfl_xor_sync(0xffffffffu, nm1, 1));
        nm1 = fmaxf(nm1, __shfl_xor_sync(0xffffffffu, nm1, 2));
        const float corr0 = __expf(m0 - nm0);
        const float corr1 = __expf(m1 - nm1);
        float rs0 = 0.f, rs1 = 0.f;
#pragma unroll
        for (int nt = 0; nt < 8; nt++) {
            accs[nt][0] = __expf(accs[nt][0] - nm0);
            accs[nt][1] = __expf(accs[nt][1] - nm0);
            accs[nt][2] = __expf(accs[nt][2] - nm1);
            accs[nt][3] = __expf(accs[nt][3] - nm1);
            rs0 += accs[nt][0] + accs[nt][1];
            rs1 += accs[nt][2] + accs[nt][3];
        }
        rs0 += __shfl_xor_sync(0xffffffffu, rs0, 1);
        rs0 += __shfl_xor_sync(0xffffffffu, rs0, 2);
        rs1 += __shfl_xor_sync(0xffffffffu, rs1, 1);
        rs1 += __shfl_xor_sync(0xffffffffu, rs1, 2);
        l0 = l0 * corr0 + rs0;
        l1 = l1 * corr1 + rs1;
        m0 = nm0; m1 = nm1;
#pragma unroll
        for (int dt = 0; dt < 8; dt++) {
            acc_o[dt][0] *= corr0;
            acc_o[dt][1] *= corr0;
            acc_o[dt][2] *= corr1;
            acc_o[dt][3] *= corr1;
        }

        // ---- PV: ph·vh + ph·vl ----
#pragma unroll
        for (int kc = 0; kc < 4; kc++) {
            uint32_t pah[4];
            pah[0] = packh(accs[2 * kc][0],     accs[2 * kc][1]);
            pah[1] = packh(accs[2 * kc][2],     accs[2 * kc][3]);
            pah[2] = packh(accs[2 * kc + 1][0], accs[2 * kc + 1][1]);
            pah[3] = packh(accs[2 * kc + 1][2], accs[2 * kc + 1][3]);
            const uint32_t vOff = kc * 32;
            uint32_t vh0[2][4], vh1[2][4], vl0[2][4], vl1[2][4];
#pragma unroll
            for (int d2 = 0; d2 < 2; d2++) {
                const uint32_t vAddr = d2 * (32 * 144) + rLane + vOff;
                ldsm4(vh0[d2], sVH + vAddr);
                ldsm4(vh1[d2], sVH + vAddr + 16);
                ldsm4(vl0[d2], sVL + vAddr);
                ldsm4(vl1[d2], sVL + vAddr + 16);
            }
#pragma unroll
            for (int d2 = 0; d2 < 2; d2++)
#pragma unroll
                for (int q = 0; q < 4; q++)
                    mmah(acc_o[d2 * 4 + q], pah[0], pah[1], pah[2], pah[3],
                         vh0[d2][q], vh1[d2][q]);
#pragma unroll
            for (int d2 = 0; d2 < 2; d2++)
#pragma unroll
                for (int q = 0; q < 4; q++)
                    mmah(acc_o[d2 * 4 + q], pah[0], pah[1], pah[2], pah[3],
                         vl0[d2][q], vl1[d2][q]);
        }

        if (lid == 0) MBAR_ARRIVE(fbar + buf * 8);
        if (tid == 0 && kt + 2 < nkt) {
            if (buf == 0) { MBAR_WAIT(fbar, fph0); fph0 ^= 1; }
            else          { MBAR_WAIT(fbar + 8, fph1); fph1 ^= 1; }
            issue_kv(buf, kt + 2);
        }
    }

    // ---- epilogue: write tiled fp16 high output (A operand of o-proj) ----
    const float inv0 = 1.f / l0;
    const float inv1 = 1.f / l1;
    const int row0 = (int)(tok_base + q0 + wrow + g);
#pragma unroll
    for (int dt = 0; dt < 8; dt++) {
        const int col = hcol + dt * 8 + tg * 2;
        uint32_t hi0 = packh(acc_o[dt][0] * inv0, acc_o[dt][1] * inv0);
        uint32_t hi1 = packh(acc_o[dt][2] * inv1, acc_o[dt][3] * inv1);
#pragma unroll
        for (int rr = 0; rr < 2; rr++) {
            const int r2 = row0 + rr * 8;
            const size_t dst = ((size_t)((r2 >> 7) * 32 + (col >> 5))) * APIECE
                             + (size_t)(r2 & 127) * GLD2 + (col & 31);
            *(uint32_t*)&oh[dst] = rr ? hi1 : hi0;
        }
    }
}

// ---------------------------------------------------------------------------
extern "C" void kernel_launch(void* const* d_in, const int* in_sizes, int n_in,
                              void* d_out, int out_size)
{
    const float* x     = (const float*)d_in[0];
    const float* w_qkv = (const float*)d_in[1];
    const float* b_qkv = (const float*)d_in[2];
    const float* w_o   = (const float*)d_in[3];
    const float* b_o   = (const float*)d_in[4];
    float* out = (float*)d_out;

    float *p_qkv;
    f16 *p_xh, *p_wqh, *p_wql, *p_woh, *p_wol;
    f16 *p_ath, *p_kh, *p_kl, *p_vh, *p_vl;
    cudaGetSymbolAddress((void**)&p_qkv, g_qkv);
    cudaGetSymbolAddress((void**)&p_xh, g_xh);
    cudaGetSymbolAddress((void**)&p_wqh, g_wqh);
    cudaGetSymbolAddress((void**)&p_wql, g_wql);
    cudaGetSymbolAddress((void**)&p_woh, g_woh);
    cudaGetSymbolAddress((void**)&p_wol, g_wol);
    cudaGetSymbolAddress((void**)&p_ath, g_ath);
    cudaGetSymbolAddress((void**)&p_kh, g_kh);
    cudaGetSymbolAddress((void**)&p_kl, g_kl);
    cudaGetSymbolAddress((void**)&p_vh, g_vh);
    cudaGetSymbolAddress((void**)&p_vl, g_vl);

    cudaFuncSetAttribute(gemm_f16, cudaFuncAttributeMaxDynamicSharedMemorySize,
                         GEMM_SMEM);
    cudaFuncSetAttribute(attn_tc, cudaFuncAttributeMaxDynamicSharedMemorySize,
                         ATT_SMEM);

    split_tiled<<<(M_TOK * HID) / 2048, 256>>>(x, p_xh, nullptr, HID);
    split_tiled<<<(N_QKV * HID) / 2048, 256>>>(w_qkv, p_wqh, p_wql, HID);
    split_tiled<<<(HID * QKV_) / 2048, 256>>>(w_o, p_woh, p_wol, QKV_);

    // 1) QKV projection (K columns emitted pre-split tiled fp16)
    {
        dim3 grid(N_QKV / 128, M_TOK / 128);
        gemm_f16<<<grid, 256, GEMM_SMEM>>>(p_xh, p_wqh, p_wql, b_qkv, p_qkv,
                                           p_kh, p_kl, M_TOK, N_QKV, HID, 1);
    }
    // V transpose+split
    {
        dim3 grid(S_ / 64, B_ * H_);
        split_vt<<<grid, 256>>>(p_qkv, p_vh, p_vl);
    }
    // 2) attention (emits tiled fp16 high output)
    {
        dim3 grid(S_ / 128, B_ * H_);
        attn_tc<<<grid, 256, ATT_SMEM>>>(p_qkv, p_kh, p_kl, p_vh, p_vl, p_ath);
    }
    // 3) output projection
    {
        dim3 grid(QKV_ / 128, M_TOK / 128);
        gemm_f16<<<grid, 256, GEMM_SMEM>>>(p_ath, p_woh, p_wol, b_o, out,
                                           nullptr, nullptr, M_TOK, QKV_, HID, 0);
    }
}

// round 15
// speedup vs baseline: 3.9779x; 1.6211x over previous
#include <cuda_runtime.h>
#include <cuda_fp16.h>
#include <math.h>
#include <stdint.h>

#define B_    2
#define S_    2048
#define H_    16
#define D_    64
#define HID   1024
#define QKV_  1024
#define M_TOK 4096
#define N_QKV 3072
#define SCALE 0.125f

typedef unsigned long long u64;
typedef __half f16;

// ---------------- helpers ----------------------------------------------------
__device__ __forceinline__ uint32_t packh(float x, float y) {
    __half2 h = __floats2half2_rn(x, y);
    return *(uint32_t*)&h;
}
__device__ __forceinline__ void mmah(float* d,
    uint32_t a0, uint32_t a1, uint32_t a2, uint32_t a3, uint32_t b0, uint32_t b1) {
    asm volatile(
        "mma.sync.aligned.m16n8k16.row.col.f32.f16.f16.f32 "
        "{%0,%1,%2,%3},{%4,%5,%6,%7},{%8,%9},{%0,%1,%2,%3};"
        : "+f"(d[0]), "+f"(d[1]), "+f"(d[2]), "+f"(d[3])
        : "r"(a0), "r"(a1), "r"(a2), "r"(a3), "r"(b0), "r"(b1));
}
__device__ __forceinline__ void ldsm4(uint32_t* r, uint32_t addr) {
    asm volatile("ldmatrix.sync.aligned.m8n8.x4.shared.b16 {%0,%1,%2,%3},[%4];"
                 : "=r"(r[0]), "=r"(r[1]), "=r"(r[2]), "=r"(r[3]) : "r"(addr));
}
__device__ __forceinline__ uint32_t smem_u32(const void* p) {
    uint32_t a;
    asm("{ .reg .u64 t; cvta.to.shared.u64 t, %1; cvt.u32.u64 %0, t; }" : "=r"(a) : "l"(p));
    return a;
}
__device__ __forceinline__ void bulkcp(uint32_t dst, const void* src,
                                       uint32_t bytes, uint32_t mbar) {
    asm volatile(
        "cp.async.bulk.shared::cluster.global.mbarrier::complete_tx::bytes "
        "[%0], [%1], %2, [%3];"
        :: "r"(dst), "l"(src), "r"(bytes), "r"(mbar) : "memory");
}
#define MBAR_INIT(a, c) \
    asm volatile("mbarrier.init.shared.b64 [%0], %1;" :: "r"(a), "r"(c) : "memory")
#define MBAR_EXPECT(a, bytes) \
    asm volatile("mbarrier.arrive.expect_tx.shared.b64 _, [%0], %1;" \
                 :: "r"(a), "r"(bytes) : "memory")
#define MBAR_ARRIVE(a) \
    asm volatile("mbarrier.arrive.shared.b64 _, [%0];" :: "r"(a) : "memory")
#define MBAR_WAIT(a, ph) do {                                                  \
    uint32_t _m = (a); uint32_t _p = (ph); uint32_t _done;                     \
    asm volatile("{ .reg .pred p; mbarrier.try_wait.parity.acquire.cta.shared::cta.b64 p, [%1], %2;" \
                 " selp.b32 %0,1,0,p; }" : "=r"(_done) : "r"(_m), "r"(_p) : "memory"); \
    if (!_done) {                                                              \
        asm volatile("{ .reg .pred P1; WL_%=:"                                 \
                     " mbarrier.try_wait.parity.acquire.cta.shared::cta.b64 P1, [%0], %1, 0x989680;" \
                     " @P1 bra.uni WD_%=; bra.uni WL_%=; WD_%=: }"             \
                     :: "r"(_m), "r"(_p) : "memory");                          \
    }                                                                          \
} while (0)

// ---------------- tiled layout constants -------------------------------------
#define GLD2 40
#define APIECE (128 * GLD2)
#define AQLD 72
#define KPIECE (128 * AQLD)
#define KSUB (64 * AQLD)
#define VP2 (64 * AQLD)

// ---------------- scratch ----------------------------------------------------
__device__ float g_qkv[(size_t)M_TOK * N_QKV];
__device__ f16 g_xh[(size_t)32 * 32 * APIECE];
__device__ f16 g_wqh[(size_t)24 * 32 * APIECE];
__device__ f16 g_woh[(size_t)8 * 32 * APIECE];
__device__ f16 g_ath[(size_t)32 * 32 * APIECE];
__device__ f16 g_kh[(size_t)512 * KPIECE];
__device__ f16 g_vh[(size_t)32 * 32 * VP2];

// ---------------------------------------------------------------------------
// split pre-pass: fp32 row-major [R][C] -> tiled fp16
// ---------------------------------------------------------------------------
__global__ __launch_bounds__(256) void split_tiled(
    const float* __restrict__ src, f16* __restrict__ h, int C)
{
    const size_t e = ((size_t)blockIdx.x * 256 + threadIdx.x) * 8;
    const int r = (int)(e / C), c = (int)(e % C);
    float4 a = *(const float4*)(src + e);
    float4 b = *(const float4*)(src + e + 4);
    const size_t dst = ((size_t)((r >> 7) * (C >> 5) + (c >> 5))) * APIECE
                     + (size_t)(r & 127) * GLD2 + (c & 31);
    *(uint4*)(h + dst) = make_uint4(packh(a.x, a.y), packh(a.z, a.w),
                                    packh(b.x, b.y), packh(b.z, b.w));
}

// V transpose: [bh][st] pieces of [64 d][72] (64 s + pad), fp16
__global__ __launch_bounds__(256) void split_vt(
    const float* __restrict__ qkv, f16* __restrict__ vh)
{
    __shared__ float T[64][65];
    const int st = blockIdx.x;
    const int bh = blockIdx.y;
    const int b = bh >> 4, h = bh & 15;
    const int s0 = st * 64;
    const int tid = threadIdx.x;
    {
        const int sl = tid >> 2;
        const int cq = tid & 3;
        const float* src = qkv + ((size_t)(b * S_ + s0 + sl)) * N_QKV
                         + 2 * QKV_ + h * D_ + cq * 16;
#pragma unroll
        for (int j = 0; j < 4; j++) {
            float4 v = *(const float4*)(src + j * 4);
            T[cq * 16 + j * 4 + 0][sl] = v.x;
            T[cq * 16 + j * 4 + 1][sl] = v.y;
            T[cq * 16 + j * 4 + 2][sl] = v.z;
            T[cq * 16 + j * 4 + 3][sl] = v.w;
        }
    }
    __syncthreads();
    const int d = tid >> 2;
    const int sq = tid & 3;
    uint32_t hh[8];
#pragma unroll
    for (int k = 0; k < 8; k++)
        hh[k] = packh(T[d][sq * 16 + 2 * k], T[d][sq * 16 + 2 * k + 1]);
    const size_t dst = (size_t)(bh * 32 + st) * VP2 + (size_t)d * AQLD + sq * 16;
    *(uint4*)(vh + dst)     = make_uint4(hh[0], hh[1], hh[2], hh[3]);
    *(uint4*)(vh + dst + 8) = make_uint4(hh[4], hh[5], hh[6], hh[7]);
}

// ---------------------------------------------------------------------------
// fp16 NT GEMM (single-term): C = A*B^T + bias ; 4-stage bulk-copy pipeline
// CTA 128x128, 8 warps (64x32), barrier-free handoff, 2 CTA/SM.
// ---------------------------------------------------------------------------
#define GT_B (128 * GLD2 * 2)          // 10240
#define STG2 (2 * GT_B)                // Ah + Bh = 20480
#define GNST 4
#define GEMM_SMEM (GNST * STG2 + 64)   // 81984

__global__ __launch_bounds__(256, 2) void gemm_f16(
    const f16* __restrict__ Ah, const f16* __restrict__ Bh,
    const float* __restrict__ bias, float* __restrict__ C,
    f16* __restrict__ kh,
    int M, int N, int K, int kmode)
{
    extern __shared__ char smem[];
    const uint32_t sb = smem_u32(smem);
    const uint32_t dbar = sb + GNST * STG2;
    const uint32_t fbar = dbar + 32;

    const int tid = threadIdx.x;
    const int wid = tid >> 5;
    const int lid = tid & 31;
    const int g   = lid >> 2;
    const int tg  = lid & 3;
    const int wm  = (wid & 1) * 64;
    const int wn  = (wid >> 1) * 32;
    const int bm  = blockIdx.y * 128;
    const int bn  = blockIdx.x * 128;

    const int kp = K >> 5;
    const f16* pAh = Ah + (size_t)blockIdx.y * kp * APIECE;
    const f16* pBh = Bh + (size_t)blockIdx.x * kp * APIECE;

    if (tid == 0) {
#pragma unroll
        for (int s = 0; s < GNST; s++) {
            MBAR_INIT(dbar + s * 8, 1);
            MBAR_INIT(fbar + s * 8, 8);
        }
    }
    __syncthreads();

    auto issue = [&](int s, int c) {
        const uint32_t mb = dbar + s * 8;
        const uint32_t d  = sb + s * STG2;
        MBAR_EXPECT(mb, STG2);
        bulkcp(d,        pAh + (size_t)c * APIECE, GT_B, mb);
        bulkcp(d + GT_B, pBh + (size_t)c * APIECE, GT_B, mb);
    };

    if (tid == 0) { issue(0, 0); issue(1, 1); issue(2, 2); }

    const uint32_t aLane = (uint32_t)((lid & 15) * GLD2 + ((lid >> 4) << 3)) * 2;
    const uint32_t bLane = (uint32_t)((wn + lid) * GLD2) * 2;

    float acc[4][4][4];
#pragma unroll
    for (int mi = 0; mi < 4; mi++)
#pragma unroll
        for (int ni = 0; ni < 4; ni++)
#pragma unroll
            for (int r = 0; r < 4; r++) acc[mi][ni][r] = 0.f;

    int dph[GNST] = {0, 0, 0, 0}, fph[GNST] = {0, 0, 0, 0};
    for (int c = 0; c < kp; c++) {
        const int s = c & 3;
        MBAR_WAIT(dbar + s * 8, dph[s]); dph[s] ^= 1;

        const uint32_t sAH = sb + s * STG2;
        const uint32_t sBH = sAH + GT_B;

#pragma unroll
        for (int k2 = 0; k2 < 2; k2++) {
            const uint32_t kOff = k2 * 32;
            uint32_t bh0[4], bh1[4];
            ldsm4(bh0, sBH + bLane + kOff);
            ldsm4(bh1, sBH + bLane + kOff + 16);
#pragma unroll
            for (int mi = 0; mi < 4; mi++) {
                const uint32_t rOff = (uint32_t)(wm + mi * 16) * 80 + aLane + kOff;
                uint32_t ah[4];
                ldsm4(ah, sAH + rOff);
#pragma unroll
                for (int ni = 0; ni < 4; ni++)
                    mmah(acc[mi][ni], ah[0], ah[1], ah[2], ah[3], bh0[ni], bh1[ni]);
            }
        }

        if (lid == 0) MBAR_ARRIVE(fbar + s * 8);
        if (tid == 0 && c + 3 < kp) {
            const int t = (c + 3) & 3;
            if (c + 3 >= GNST) { MBAR_WAIT(fbar + t * 8, fph[t]); fph[t] ^= 1; }
            issue(t, c + 3);
        }
    }

    const bool ksplit = kmode && (bn >= QKV_) && (bn < 2 * QKV_);
    if (ksplit) {
#pragma unroll
        for (int ni = 0; ni < 4; ni++) {
            const int col = bn + wn + ni * 8 + tg * 2;
            const float bx = bias[col], by = bias[col + 1];
            const int colq = col - QKV_;
            const int hh = colq >> 6, dd = colq & 63;
#pragma unroll
            for (int mi = 0; mi < 4; mi++) {
                const int row = bm + wm + mi * 16 + g;
                uint32_t hi0 = packh(acc[mi][ni][0] + bx, acc[mi][ni][1] + by);
                uint32_t hi1 = packh(acc[mi][ni][2] + bx, acc[mi][ni][3] + by);
#pragma unroll
                for (int rr = 0; rr < 2; rr++) {
                    const int r2 = row + rr * 8;
                    const size_t dst =
                        (size_t)((((r2 >> 11) << 4) + hh) * 16 + ((r2 >> 7) & 15)) * KPIECE
                        + (size_t)(r2 & 127) * AQLD + dd;
                    *(uint32_t*)&kh[dst] = rr ? hi1 : hi0;
                }
            }
        }
    } else {
#pragma unroll
        for (int ni = 0; ni < 4; ni++) {
            const int col = bn + wn + ni * 8 + tg * 2;
            const float bx = bias[col], by = bias[col + 1];
#pragma unroll
            for (int mi = 0; mi < 4; mi++) {
                const int row = bm + wm + mi * 16 + g;
                float2 w0, w1;
                w0.x = acc[mi][ni][0] + bx;
                w0.y = acc[mi][ni][1] + by;
                w1.x = acc[mi][ni][2] + bx;
                w1.y = acc[mi][ni][3] + by;
                *(float2*)&C[(size_t)row * N + col]       = w0;
                *(float2*)&C[(size_t)(row + 8) * N + col] = w1;
            }
        }
    }
}

// ---------------------------------------------------------------------------
// fp16 flash attention (single-term): KV tile 64, 4-stage pipeline, 2 CTA/SM
// ---------------------------------------------------------------------------
#define QT_B (128 * AQLD * 2)       // 18432
#define KT2_B (64 * AQLD * 2)       // 9216
#define AST_B (2 * KT2_B)           // K + V per stage = 18432
#define ANST 4
#define OFF_K0 QT_B
#define ATT_MB (QT_B + ANST * AST_B)    // 92160
#define ATT_SMEM (ATT_MB + 64)          // 92224

__global__ __launch_bounds__(256, 2) void attn_tc(
    const float* __restrict__ qkv,
    const f16* __restrict__ kh_g, const f16* __restrict__ vh_g,
    f16* __restrict__ oh)
{
    extern __shared__ char smc[];
    const uint32_t sb = smem_u32(smc);
    const uint32_t dbar = sb + ATT_MB;
    const uint32_t fbar = dbar + 32;
    f16* Qh = (f16*)smc;

    const int tid = threadIdx.x;
    const int wid = tid >> 5;
    const int lid = tid & 31;
    const int g   = lid >> 2;
    const int tg  = lid & 3;
    const int qt  = blockIdx.x;
    const int bhx = blockIdx.y;
    const int b   = bhx >> 4;
    const int q0  = qt * 128;
    const size_t tok_base = (size_t)b * S_;
    const int hcol = (bhx & 15) * D_;
    const int wrow = wid * 16;

    if (tid == 0) {
#pragma unroll
        for (int s = 0; s < ANST; s++) {
            MBAR_INIT(dbar + s * 8, 1);
            MBAR_INIT(fbar + s * 8, 8);
        }
    }

    // Q load: fp32 -> scaled fp16
    {
        const int lr  = tid >> 1;
        const int lch = (tid & 1) * 32;
        const float* qp = qkv + (tok_base + q0 + lr) * (size_t)N_QKV + hcol + lch;
        const int base = lr * AQLD + lch;
#pragma unroll
        for (int j = 0; j < 8; j++) {
            float4 v = *(const float4*)(qp + j * 4);
            *(uint32_t*)&Qh[base + j * 4]     = packh(v.x * SCALE, v.y * SCALE);
            *(uint32_t*)&Qh[base + j * 4 + 2] = packh(v.z * SCALE, v.w * SCALE);
        }
    }
    __syncthreads();

    const f16* pKh = kh_g + (size_t)bhx * 16 * KPIECE;
    const f16* pVh = vh_g + (size_t)bhx * 32 * VP2;

    auto issue_kv = [&](int s, int kt) {
        const uint32_t mb  = dbar + s * 8;
        const uint32_t dkb = sb + OFF_K0 + s * AST_B;
        MBAR_EXPECT(mb, AST_B);
        bulkcp(dkb,         pKh + (size_t)kt * KSUB, KT2_B, mb);
        bulkcp(dkb + KT2_B, pVh + (size_t)kt * VP2,  KT2_B, mb);
    };

    if (tid == 0) { issue_kv(0, 0); issue_kv(1, 1); issue_kv(2, 2); }

    const uint32_t qLane = (uint32_t)((wrow + (lid & 15)) * AQLD + ((lid >> 4) << 3)) * 2;
    const uint32_t rLane = (uint32_t)lid * 144;

    float acc_o[8][4];
#pragma unroll
    for (int dt = 0; dt < 8; dt++)
#pragma unroll
        for (int r = 0; r < 4; r++) acc_o[dt][r] = 0.f;
    float m0 = -INFINITY, m1 = -INFINITY, l0 = 0.f, l1 = 0.f;

    int dph[ANST] = {0, 0, 0, 0}, fph[ANST] = {0, 0, 0, 0};
    const int nkt = S_ / 64;
    for (int kt = 0; kt < nkt; kt++) {
        const int s = kt & 3;
        MBAR_WAIT(dbar + s * 8, dph[s]); dph[s] ^= 1;

        const uint32_t sKH = sb + OFF_K0 + s * AST_B;
        const uint32_t sVH = sKH + KT2_B;

        // ---- scores: q·k (single term) ----
        float accs[8][4];
#pragma unroll
        for (int nt = 0; nt < 8; nt++)
#pragma unroll
            for (int r = 0; r < 4; r++) accs[nt][r] = 0.f;

#pragma unroll
        for (int ks = 0; ks < 4; ks++) {
            const uint32_t kOff = ks * 32;
            uint32_t ah[4];
            ldsm4(ah, sb + qLane + kOff);
            uint32_t kh0[2][4], kh1[2][4];
#pragma unroll
            for (int n2 = 0; n2 < 2; n2++) {
                const uint32_t kAddr = n2 * (32 * 144) + rLane + kOff;
                ldsm4(kh0[n2], sKH + kAddr);
                ldsm4(kh1[n2], sKH + kAddr + 16);
            }
#pragma unroll
            for (int n2 = 0; n2 < 2; n2++)
#pragma unroll
                for (int q = 0; q < 4; q++)
                    mmah(accs[n2 * 4 + q], ah[0], ah[1], ah[2], ah[3],
                         kh0[n2][q], kh1[n2][q]);
        }

        // ---- online softmax ----
        float nm0 = m0, nm1 = m1;
#pragma unroll
        for (int nt = 0; nt < 8; nt++) {
            nm0 = fmaxf(nm0, fmaxf(accs[nt][0], accs[nt][1]));
            nm1 = fmaxf(nm1, fmaxf(accs[nt][2], accs[nt][3]));
        }
        nm0 = fmaxf(nm0, __shfl_xor_sync(0xffffffffu, nm0, 1));
        nm0 = fmaxf(nm0, __shfl_xor_sync(0xffffffffu, nm0, 2));
        nm1 = fmaxf(nm1, __shfl_xor_sync(0xffffffffu, nm1, 1));
        nm1 = fmaxf(nm1, __shfl_xor_sync(0xffffffffu, nm1, 2));
        const float corr0 = __expf(m0 - nm0);
        const float corr1 = __expf(m1 - nm1);
        float rs0 = 0.f, rs1 = 0.f;
#pragma unroll
        for (int nt = 0; nt < 8; nt++) {
            accs[nt][0] = __expf(accs[nt][0] - nm0);
            accs[nt][1] = __expf(accs[nt][1] - nm0);
            accs[nt][2] = __expf(accs[nt][2] - nm1);
            accs[nt][3] = __expf(accs[nt][3] - nm1);
            rs0 += accs[nt][0] + accs[nt][1];
            rs1 += accs[nt][2] + accs[nt][3];
        }
        rs0 += __shfl_xor_sync(0xffffffffu, rs0, 1);
        rs0 += __shfl_xor_sync(0xffffffffu, rs0, 2);
        rs1 += __shfl_xor_sync(0xffffffffu, rs1, 1);
        rs1 += __shfl_xor_sync(0xffffffffu, rs1, 2);
        l0 = l0 * corr0 + rs0;
        l1 = l1 * corr1 + rs1;
        m0 = nm0; m1 = nm1;
#pragma unroll
        for (int dt = 0; dt < 8; dt++) {
            acc_o[dt][0] *= corr0;
            acc_o[dt][1] *= corr0;
            acc_o[dt][2] *= corr1;
            acc_o[dt][3] *= corr1;
        }

        // ---- PV: p·v (single term) ----
#pragma unroll
        for (int kc = 0; kc < 4; kc++) {
            uint32_t pah[4];
            pah[0] = packh(accs[2 * kc][0],     accs[2 * kc][1]);
            pah[1] = packh(accs[2 * kc][2],     accs[2 * kc][3]);
            pah[2] = packh(accs[2 * kc + 1][0], accs[2 * kc + 1][1]);
            pah[3] = packh(accs[2 * kc + 1][2], accs[2 * kc + 1][3]);
            const uint32_t vOff = kc * 32;
            uint32_t vh0[2][4], vh1[2][4];
#pragma unroll
            for (int d2 = 0; d2 < 2; d2++) {
                const uint32_t vAddr = d2 * (32 * 144) + rLane + vOff;
                ldsm4(vh0[d2], sVH + vAddr);
                ldsm4(vh1[d2], sVH + vAddr + 16);
            }
#pragma unroll
            for (int d2 = 0; d2 < 2; d2++)
#pragma unroll
                for (int q = 0; q < 4; q++)
                    mmah(acc_o[d2 * 4 + q], pah[0], pah[1], pah[2], pah[3],
                         vh0[d2][q], vh1[d2][q]);
        }

        if (lid == 0) MBAR_ARRIVE(fbar + s * 8);
        if (tid == 0 && kt + 3 < nkt) {
            const int t = (kt + 3) & 3;
            if (kt + 3 >= ANST) { MBAR_WAIT(fbar + t * 8, fph[t]); fph[t] ^= 1; }
            issue_kv(t, kt + 3);
        }
    }

    // ---- epilogue: write tiled fp16 output (A operand of o-proj) ----
    const float inv0 = 1.f / l0;
    const float inv1 = 1.f / l1;
    const int row0 = (int)(tok_base + q0 + wrow + g);
#pragma unroll
    for (int dt = 0; dt < 8; dt++) {
        const int col = hcol + dt * 8 + tg * 2;
        uint32_t hi0 = packh(acc_o[dt][0] * inv0, acc_o[dt][1] * inv0);
        uint32_t hi1 = packh(acc_o[dt][2] * inv1, acc_o[dt][3] * inv1);
#pragma unroll
        for (int rr = 0; rr < 2; rr++) {
            const int r2 = row0 + rr * 8;
            const size_t dst = ((size_t)((r2 >> 7) * 32 + (col >> 5))) * APIECE
                             + (size_t)(r2 & 127) * GLD2 + (col & 31);
            *(uint32_t*)&oh[dst] = rr ? hi1 : hi0;
        }
    }
}

// ---------------------------------------------------------------------------
extern "C" void kernel_launch(void* const* d_in, const int* in_sizes, int n_in,
                              void* d_out, int out_size)
{
    const float* x     = (const float*)d_in[0];
    const float* w_qkv = (const float*)d_in[1];
    const float* b_qkv = (const float*)d_in[2];
    const float* w_o   = (const float*)d_in[3];
    const float* b_o   = (const float*)d_in[4];
    float* out = (float*)d_out;

    float *p_qkv;
    f16 *p_xh, *p_wqh, *p_woh, *p_ath, *p_kh, *p_vh;
    cudaGetSymbolAddress((void**)&p_qkv, g_qkv);
    cudaGetSymbolAddress((void**)&p_xh, g_xh);
    cudaGetSymbolAddress((void**)&p_wqh, g_wqh);
    cudaGetSymbolAddress((void**)&p_woh, g_woh);
    cudaGetSymbolAddress((void**)&p_ath, g_ath);
    cudaGetSymbolAddress((void**)&p_kh, g_kh);
    cudaGetSymbolAddress((void**)&p_vh, g_vh);

    cudaFuncSetAttribute(gemm_f16, cudaFuncAttributeMaxDynamicSharedMemorySize,
                         GEMM_SMEM);
    cudaFuncSetAttribute(attn_tc, cudaFuncAttributeMaxDynamicSharedMemorySize,
                         ATT_SMEM);

    split_tiled<<<(M_TOK * HID) / 2048, 256>>>(x, p_xh, HID);
    split_tiled<<<(N_QKV * HID) / 2048, 256>>>(w_qkv, p_wqh, HID);
    split_tiled<<<(HID * QKV_) / 2048, 256>>>(w_o, p_woh, QKV_);

    // 1) QKV projection (K columns emitted tiled fp16)
    {
        dim3 grid(N_QKV / 128, M_TOK / 128);
        gemm_f16<<<grid, 256, GEMM_SMEM>>>(p_xh, p_wqh, b_qkv, p_qkv, p_kh,
                                           M_TOK, N_QKV, HID, 1);
    }
    // V transpose
    {
        dim3 grid(S_ / 64, B_ * H_);
        split_vt<<<grid, 256>>>(p_qkv, p_vh);
    }
    // 2) attention (emits tiled fp16 output)
    {
        dim3 grid(S_ / 128, B_ * H_);
        attn_tc<<<grid, 256, ATT_SMEM>>>(p_qkv, p_kh, p_vh, p_ath);
    }
    // 3) output projection
    {
        dim3 grid(QKV_ / 128, M_TOK / 128);
        gemm_f16<<<grid, 256, GEMM_SMEM>>>(p_ath, p_woh, b_o, out, nullptr,
                                           M_TOK, QKV_, HID, 0);
    }
}

// round 16
// speedup vs baseline: 4.1621x; 1.0463x over previous
#include <cuda_runtime.h>
#include <cuda_fp16.h>
#include <math.h>
#include <stdint.h>

#define B_    2
#define S_    2048
#define H_    16
#define D_    64
#define HID   1024
#define QKV_  1024
#define M_TOK 4096
#define N_QKV 3072
#define SCALE 0.125f

typedef unsigned long long u64;
typedef __half f16;

// ---------------- helpers ----------------------------------------------------
__device__ __forceinline__ uint32_t packh(float x, float y) {
    __half2 h = __floats2half2_rn(x, y);
    return *(uint32_t*)&h;
}
__device__ __forceinline__ void mmah(float* d,
    uint32_t a0, uint32_t a1, uint32_t a2, uint32_t a3, uint32_t b0, uint32_t b1) {
    asm volatile(
        "mma.sync.aligned.m16n8k16.row.col.f32.f16.f16.f32 "
        "{%0,%1,%2,%3},{%4,%5,%6,%7},{%8,%9},{%0,%1,%2,%3};"
        : "+f"(d[0]), "+f"(d[1]), "+f"(d[2]), "+f"(d[3])
        : "r"(a0), "r"(a1), "r"(a2), "r"(a3), "r"(b0), "r"(b1));
}
__device__ __forceinline__ void ldsm4(uint32_t* r, uint32_t addr) {
    asm volatile("ldmatrix.sync.aligned.m8n8.x4.shared.b16 {%0,%1,%2,%3},[%4];"
                 : "=r"(r[0]), "=r"(r[1]), "=r"(r[2]), "=r"(r[3]) : "r"(addr));
}
__device__ __forceinline__ void ldsm4t(uint32_t* r, uint32_t addr) {
    asm volatile("ldmatrix.sync.aligned.m8n8.x4.trans.shared.b16 {%0,%1,%2,%3},[%4];"
                 : "=r"(r[0]), "=r"(r[1]), "=r"(r[2]), "=r"(r[3]) : "r"(addr));
}
__device__ __forceinline__ uint32_t smem_u32(const void* p) {
    uint32_t a;
    asm("{ .reg .u64 t; cvta.to.shared.u64 t, %1; cvt.u32.u64 %0, t; }" : "=r"(a) : "l"(p));
    return a;
}
__device__ __forceinline__ void bulkcp(uint32_t dst, const void* src,
                                       uint32_t bytes, uint32_t mbar) {
    asm volatile(
        "cp.async.bulk.shared::cluster.global.mbarrier::complete_tx::bytes "
        "[%0], [%1], %2, [%3];"
        :: "r"(dst), "l"(src), "r"(bytes), "r"(mbar) : "memory");
}
#define MBAR_INIT(a, c) \
    asm volatile("mbarrier.init.shared.b64 [%0], %1;" :: "r"(a), "r"(c) : "memory")
#define MBAR_EXPECT(a, bytes) \
    asm volatile("mbarrier.arrive.expect_tx.shared.b64 _, [%0], %1;" \
                 :: "r"(a), "r"(bytes) : "memory")
#define MBAR_ARRIVE(a) \
    asm volatile("mbarrier.arrive.shared.b64 _, [%0];" :: "r"(a) : "memory")
#define MBAR_WAIT(a, ph) do {                                                  \
    uint32_t _m = (a); uint32_t _p = (ph); uint32_t _done;                     \
    asm volatile("{ .reg .pred p; mbarrier.try_wait.parity.acquire.cta.shared::cta.b64 p, [%1], %2;" \
                 " selp.b32 %0,1,0,p; }" : "=r"(_done) : "r"(_m), "r"(_p) : "memory"); \
    if (!_done) {                                                              \
        asm volatile("{ .reg .pred P1; WL_%=:"                                 \
                     " mbarrier.try_wait.parity.acquire.cta.shared::cta.b64 P1, [%0], %1, 0x989680;" \
                     " @P1 bra.uni WD_%=; bra.uni WL_%=; WD_%=: }"             \
                     :: "r"(_m), "r"(_p) : "memory");                          \
    }                                                                          \
} while (0)

// ---------------- tiled layout constants -------------------------------------
#define GLD2 40
#define APIECE (128 * GLD2)
#define AQLD 72
#define KPIECE (128 * AQLD)   // token-major 128x72 fp16 piece (Q, K, V all use this)
#define KSUB (64 * AQLD)

// ---------------- scratch ----------------------------------------------------
__device__ f16 g_xh[(size_t)32 * 32 * APIECE];
__device__ f16 g_wqh[(size_t)24 * 32 * APIECE];
__device__ f16 g_woh[(size_t)8 * 32 * APIECE];
__device__ f16 g_ath[(size_t)32 * 32 * APIECE];
__device__ f16 g_qh[(size_t)512 * KPIECE];
__device__ f16 g_kh[(size_t)512 * KPIECE];
__device__ f16 g_vh[(size_t)512 * KPIECE];

// ---------------------------------------------------------------------------
// split pre-pass: fp32 row-major [R][C] -> tiled fp16
// ---------------------------------------------------------------------------
__global__ __launch_bounds__(256) void split_tiled(
    const float* __restrict__ src, f16* __restrict__ h, int C)
{
    const size_t e = ((size_t)blockIdx.x * 256 + threadIdx.x) * 8;
    const int r = (int)(e / C), c = (int)(e % C);
    float4 a = *(const float4*)(src + e);
    float4 b = *(const float4*)(src + e + 4);
    const size_t dst = ((size_t)((r >> 7) * (C >> 5) + (c >> 5))) * APIECE
                     + (size_t)(r & 127) * GLD2 + (c & 31);
    *(uint4*)(h + dst) = make_uint4(packh(a.x, a.y), packh(a.z, a.w),
                                    packh(b.x, b.y), packh(b.z, b.w));
}

// ---------------------------------------------------------------------------
// fp16 NT GEMM (single-term): 4-stage bulk-copy pipeline, 2 CTA/SM.
// kmode=1 (QKV proj): epilogue emits Q (scaled), K, V as fp16 tiled pieces.
// kmode=0 (O proj):   epilogue writes fp32 C + bias.
// ---------------------------------------------------------------------------
#define GT_B (128 * GLD2 * 2)
#define STG2 (2 * GT_B)
#define GNST 4
#define GEMM_SMEM (GNST * STG2 + 64)

__global__ __launch_bounds__(256, 2) void gemm_f16(
    const f16* __restrict__ Ah, const f16* __restrict__ Bh,
    const float* __restrict__ bias, float* __restrict__ C,
    f16* __restrict__ qh, f16* __restrict__ kh, f16* __restrict__ vh,
    int M, int N, int K, int kmode)
{
    extern __shared__ char smem[];
    const uint32_t sb = smem_u32(smem);
    const uint32_t dbar = sb + GNST * STG2;
    const uint32_t fbar = dbar + 32;

    const int tid = threadIdx.x;
    const int wid = tid >> 5;
    const int lid = tid & 31;
    const int g   = lid >> 2;
    const int tg  = lid & 3;
    const int wm  = (wid & 1) * 64;
    const int wn  = (wid >> 1) * 32;
    const int bm  = blockIdx.y * 128;
    const int bn  = blockIdx.x * 128;

    const int kp = K >> 5;
    const f16* pAh = Ah + (size_t)blockIdx.y * kp * APIECE;
    const f16* pBh = Bh + (size_t)blockIdx.x * kp * APIECE;

    if (tid == 0) {
#pragma unroll
        for (int s = 0; s < GNST; s++) {
            MBAR_INIT(dbar + s * 8, 1);
            MBAR_INIT(fbar + s * 8, 8);
        }
    }
    __syncthreads();

    auto issue = [&](int s, int c) {
        const uint32_t mb = dbar + s * 8;
        const uint32_t d  = sb + s * STG2;
        MBAR_EXPECT(mb, STG2);
        bulkcp(d,        pAh + (size_t)c * APIECE, GT_B, mb);
        bulkcp(d + GT_B, pBh + (size_t)c * APIECE, GT_B, mb);
    };

    if (tid == 0) { issue(0, 0); issue(1, 1); issue(2, 2); }

    const uint32_t aLane = (uint32_t)((lid & 15) * GLD2 + ((lid >> 4) << 3)) * 2;
    const uint32_t bLane = (uint32_t)((wn + lid) * GLD2) * 2;

    float acc[4][4][4];
#pragma unroll
    for (int mi = 0; mi < 4; mi++)
#pragma unroll
        for (int ni = 0; ni < 4; ni++)
#pragma unroll
            for (int r = 0; r < 4; r++) acc[mi][ni][r] = 0.f;

    int dph[GNST] = {0, 0, 0, 0}, fph[GNST] = {0, 0, 0, 0};
    for (int c = 0; c < kp; c++) {
        const int s = c & 3;
        MBAR_WAIT(dbar + s * 8, dph[s]); dph[s] ^= 1;

        const uint32_t sAH = sb + s * STG2;
        const uint32_t sBH = sAH + GT_B;

#pragma unroll
        for (int k2 = 0; k2 < 2; k2++) {
            const uint32_t kOff = k2 * 32;
            uint32_t bh0[4], bh1[4];
            ldsm4(bh0, sBH + bLane + kOff);
            ldsm4(bh1, sBH + bLane + kOff + 16);
#pragma unroll
            for (int mi = 0; mi < 4; mi++) {
                const uint32_t rOff = (uint32_t)(wm + mi * 16) * 80 + aLane + kOff;
                uint32_t ah[4];
                ldsm4(ah, sAH + rOff);
#pragma unroll
                for (int ni = 0; ni < 4; ni++)
                    mmah(acc[mi][ni], ah[0], ah[1], ah[2], ah[3], bh0[ni], bh1[ni]);
            }
        }

        if (lid == 0) MBAR_ARRIVE(fbar + s * 8);
        if (tid == 0 && c + 3 < kp) {
            const int t = (c + 3) & 3;
            if (c + 3 >= GNST) { MBAR_WAIT(fbar + t * 8, fph[t]); fph[t] ^= 1; }
            issue(t, c + 3);
        }
    }

    if (kmode) {
        // all 3 regions -> fp16 tiled pieces (token-major [tok][64d])
        const int reg = bn >> 10;                // 0=Q, 1=K, 2=V
        f16* dbuf = (reg == 0) ? qh : ((reg == 1) ? kh : vh);
        const float scl = (reg == 0) ? SCALE : 1.f;
#pragma unroll
        for (int ni = 0; ni < 4; ni++) {
            const int col = bn + wn + ni * 8 + tg * 2;
            const float bx = bias[col], by = bias[col + 1];
            const int colq = col & 1023;
            const int hh = colq >> 6, dd = colq & 63;
#pragma unroll
            for (int mi = 0; mi < 4; mi++) {
                const int row = bm + wm + mi * 16 + g;
                uint32_t hi0 = packh((acc[mi][ni][0] + bx) * scl,
                                     (acc[mi][ni][1] + by) * scl);
                uint32_t hi1 = packh((acc[mi][ni][2] + bx) * scl,
                                     (acc[mi][ni][3] + by) * scl);
#pragma unroll
                for (int rr = 0; rr < 2; rr++) {
                    const int r2 = row + rr * 8;
                    const size_t dst =
                        (size_t)((((r2 >> 11) << 4) + hh) * 16 + ((r2 >> 7) & 15)) * KPIECE
                        + (size_t)(r2 & 127) * AQLD + dd;
                    *(uint32_t*)&dbuf[dst] = rr ? hi1 : hi0;
                }
            }
        }
    } else {
#pragma unroll
        for (int ni = 0; ni < 4; ni++) {
            const int col = bn + wn + ni * 8 + tg * 2;
            const float bx = bias[col], by = bias[col + 1];
#pragma unroll
            for (int mi = 0; mi < 4; mi++) {
                const int row = bm + wm + mi * 16 + g;
                float2 w0, w1;
                w0.x = acc[mi][ni][0] + bx;
                w0.y = acc[mi][ni][1] + by;
                w1.x = acc[mi][ni][2] + bx;
                w1.y = acc[mi][ni][3] + by;
                *(float2*)&C[(size_t)row * N + col]       = w0;
                *(float2*)&C[(size_t)(row + 8) * N + col] = w1;
            }
        }
    }
}

// ---------------------------------------------------------------------------
// fp16 flash attention: Q via bulkcp (pre-scaled tiles), V token-major with
// ldmatrix.trans fragments. KV tile 64, 4-stage pipeline, 2 CTA/SM.
// ---------------------------------------------------------------------------
#define QT_B (128 * AQLD * 2)       // 18432
#define KT2_B (64 * AQLD * 2)       // 9216
#define AST_B (2 * KT2_B)
#define ANST 4
#define OFF_K0 QT_B
#define ATT_MB (QT_B + ANST * AST_B)
#define ATT_SMEM (ATT_MB + 96)

__global__ __launch_bounds__(256, 2) void attn_tc(
    const f16* __restrict__ qh_g,
    const f16* __restrict__ kh_g, const f16* __restrict__ vh_g,
    f16* __restrict__ oh)
{
    extern __shared__ char smc[];
    const uint32_t sb = smem_u32(smc);
    const uint32_t dbar = sb + ATT_MB;
    const uint32_t fbar = dbar + 32;
    const uint32_t qbar = fbar + 32;

    const int tid = threadIdx.x;
    const int wid = tid >> 5;
    const int lid = tid & 31;
    const int g   = lid >> 2;
    const int tg  = lid & 3;
    const int qt  = blockIdx.x;
    const int bhx = blockIdx.y;
    const int b   = bhx >> 4;
    const int q0  = qt * 128;
    const size_t tok_base = (size_t)b * S_;
    const int hcol = (bhx & 15) * D_;
    const int wrow = wid * 16;

    if (tid == 0) {
#pragma unroll
        for (int s = 0; s < ANST; s++) {
            MBAR_INIT(dbar + s * 8, 1);
            MBAR_INIT(fbar + s * 8, 8);
        }
        MBAR_INIT(qbar, 1);
    }
    __syncthreads();

    const f16* pKh = kh_g + (size_t)bhx * 16 * KPIECE;
    const f16* pVh = vh_g + (size_t)bhx * 16 * KPIECE;

    auto issue_kv = [&](int s, int kt) {
        const uint32_t mb  = dbar + s * 8;
        const uint32_t dkb = sb + OFF_K0 + s * AST_B;
        MBAR_EXPECT(mb, AST_B);
        bulkcp(dkb,         pKh + (size_t)kt * KSUB, KT2_B, mb);
        bulkcp(dkb + KT2_B, pVh + (size_t)kt * KSUB, KT2_B, mb);
    };

    if (tid == 0) {
        MBAR_EXPECT(qbar, QT_B);
        bulkcp(sb, qh_g + ((size_t)bhx * 16 + qt) * KPIECE, QT_B, qbar);
        issue_kv(0, 0); issue_kv(1, 1); issue_kv(2, 2);
    }
    MBAR_WAIT(qbar, 0);

    const uint32_t qLane = (uint32_t)((wrow + (lid & 15)) * AQLD + ((lid >> 4) << 3)) * 2;
    const uint32_t rLane = (uint32_t)lid * 144;                       // K rows
    const uint32_t vLane = (uint32_t)(lid & 15) * 144 + ((lid >> 4) << 4);  // V trans

    float acc_o[8][4];
#pragma unroll
    for (int dt = 0; dt < 8; dt++)
#pragma unroll
        for (int r = 0; r < 4; r++) acc_o[dt][r] = 0.f;
    float m0 = -INFINITY, m1 = -INFINITY, l0 = 0.f, l1 = 0.f;

    int dph[ANST] = {0, 0, 0, 0}, fph[ANST] = {0, 0, 0, 0};
    const int nkt = S_ / 64;
    for (int kt = 0; kt < nkt; kt++) {
        const int s = kt & 3;
        MBAR_WAIT(dbar + s * 8, dph[s]); dph[s] ^= 1;

        const uint32_t sKH = sb + OFF_K0 + s * AST_B;
        const uint32_t sVH = sKH + KT2_B;

        // ---- scores: q·k ----
        float accs[8][4];
#pragma unroll
        for (int nt = 0; nt < 8; nt++)
#pragma unroll
            for (int r = 0; r < 4; r++) accs[nt][r] = 0.f;

#pragma unroll
        for (int ks = 0; ks < 4; ks++) {
            const uint32_t kOff = ks * 32;
            uint32_t ah[4];
            ldsm4(ah, sb + qLane + kOff);
            uint32_t kh0[2][4], kh1[2][4];
#pragma unroll
            for (int n2 = 0; n2 < 2; n2++) {
                const uint32_t kAddr = n2 * (32 * 144) + rLane + kOff;
                ldsm4(kh0[n2], sKH + kAddr);
                ldsm4(kh1[n2], sKH + kAddr + 16);
            }
#pragma unroll
            for (int n2 = 0; n2 < 2; n2++)
#pragma unroll
                for (int q = 0; q < 4; q++)
                    mmah(accs[n2 * 4 + q], ah[0], ah[1], ah[2], ah[3],
                         kh0[n2][q], kh1[n2][q]);
        }

        // ---- online softmax ----
        float nm0 = m0, nm1 = m1;
#pragma unroll
        for (int nt = 0; nt < 8; nt++) {
            nm0 = fmaxf(nm0, fmaxf(accs[nt][0], accs[nt][1]));
            nm1 = fmaxf(nm1, fmaxf(accs[nt][2], accs[nt][3]));
        }
        nm0 = fmaxf(nm0, __shfl_xor_sync(0xffffffffu, nm0, 1));
        nm0 = fmaxf(nm0, __shfl_xor_sync(0xffffffffu, nm0, 2));
        nm1 = fmaxf(nm1, __shfl_xor_sync(0xffffffffu, nm1, 1));
        nm1 = fmaxf(nm1, __shfl_xor_sync(0xffffffffu, nm1, 2));
        const float corr0 = __expf(m0 - nm0);
        const float corr1 = __expf(m1 - nm1);
        float rs0 = 0.f, rs1 = 0.f;
#pragma unroll
        for (int nt = 0; nt < 8; nt++) {
            accs[nt][0] = __expf(accs[nt][0] - nm0);
            accs[nt][1] = __expf(accs[nt][1] - nm0);
            accs[nt][2] = __expf(accs[nt][2] - nm1);
            accs[nt][3] = __expf(accs[nt][3] - nm1);
            rs0 += accs[nt][0] + accs[nt][1];
            rs1 += accs[nt][2] + accs[nt][3];
        }
        rs0 += __shfl_xor_sync(0xffffffffu, rs0, 1);
        rs0 += __shfl_xor_sync(0xffffffffu, rs0, 2);
        rs1 += __shfl_xor_sync(0xffffffffu, rs1, 1);
        rs1 += __shfl_xor_sync(0xffffffffu, rs1, 2);
        l0 = l0 * corr0 + rs0;
        l1 = l1 * corr1 + rs1;
        m0 = nm0; m1 = nm1;
#pragma unroll
        for (int dt = 0; dt < 8; dt++) {
            acc_o[dt][0] *= corr0;
            acc_o[dt][1] *= corr0;
            acc_o[dt][2] *= corr1;
            acc_o[dt][3] *= corr1;
        }

        // ---- PV: p·v, V token-major via ldmatrix.trans ----
#pragma unroll
        for (int kc = 0; kc < 4; kc++) {
            uint32_t pah[4];
            pah[0] = packh(accs[2 * kc][0],     accs[2 * kc][1]);
            pah[1] = packh(accs[2 * kc][2],     accs[2 * kc][3]);
            pah[2] = packh(accs[2 * kc + 1][0], accs[2 * kc + 1][1]);
            pah[3] = packh(accs[2 * kc + 1][2], accs[2 * kc + 1][3]);
            const uint32_t vBase = sVH + (uint32_t)(kc * 16) * 144 + vLane;
#pragma unroll
            for (int d2 = 0; d2 < 2; d2++) {
#pragma unroll
                for (int u = 0; u < 2; u++) {
                    uint32_t vr[4];
                    ldsm4t(vr, vBase + d2 * 64 + u * 32);
                    const int nt = d2 * 4 + u * 2;
                    mmah(acc_o[nt],     pah[0], pah[1], pah[2], pah[3], vr[0], vr[1]);
                    mmah(acc_o[nt + 1], pah[0], pah[1], pah[2], pah[3], vr[2], vr[3]);
                }
            }
        }

        if (lid == 0) MBAR_ARRIVE(fbar + s * 8);
        if (tid == 0 && kt + 3 < nkt) {
            const int t = (kt + 3) & 3;
            if (kt + 3 >= ANST) { MBAR_WAIT(fbar + t * 8, fph[t]); fph[t] ^= 1; }
            issue_kv(t, kt + 3);
        }
    }

    // ---- epilogue: write tiled fp16 output (A operand of o-proj) ----
    const float inv0 = 1.f / l0;
    const float inv1 = 1.f / l1;
    const int row0 = (int)(tok_base + q0 + wrow + g);
#pragma unroll
    for (int dt = 0; dt < 8; dt++) {
        const int col = hcol + dt * 8 + tg * 2;
        uint32_t hi0 = packh(acc_o[dt][0] * inv0, acc_o[dt][1] * inv0);
        uint32_t hi1 = packh(acc_o[dt][2] * inv1, acc_o[dt][3] * inv1);
#pragma unroll
        for (int rr = 0; rr < 2; rr++) {
            const int r2 = row0 + rr * 8;
            const size_t dst = ((size_t)((r2 >> 7) * 32 + (col >> 5))) * APIECE
                             + (size_t)(r2 & 127) * GLD2 + (col & 31);
            *(uint32_t*)&oh[dst] = rr ? hi1 : hi0;
        }
    }
}

// ---------------------------------------------------------------------------
extern "C" void kernel_launch(void* const* d_in, const int* in_sizes, int n_in,
                              void* d_out, int out_size)
{
    const float* x     = (const float*)d_in[0];
    const float* w_qkv = (const float*)d_in[1];
    const float* b_qkv = (const float*)d_in[2];
    const float* w_o   = (const float*)d_in[3];
    const float* b_o   = (const float*)d_in[4];
    float* out = (float*)d_out;

    f16 *p_xh, *p_wqh, *p_woh, *p_ath, *p_qh, *p_kh, *p_vh;
    cudaGetSymbolAddress((void**)&p_xh, g_xh);
    cudaGetSymbolAddress((void**)&p_wqh, g_wqh);
    cudaGetSymbolAddress((void**)&p_woh, g_woh);
    cudaGetSymbolAddress((void**)&p_ath, g_ath);
    cudaGetSymbolAddress((void**)&p_qh, g_qh);
    cudaGetSymbolAddress((void**)&p_kh, g_kh);
    cudaGetSymbolAddress((void**)&p_vh, g_vh);

    cudaFuncSetAttribute(gemm_f16, cudaFuncAttributeMaxDynamicSharedMemorySize,
                         GEMM_SMEM);
    cudaFuncSetAttribute(attn_tc, cudaFuncAttributeMaxDynamicSharedMemorySize,
                         ATT_SMEM);

    split_tiled<<<(M_TOK * HID) / 2048, 256>>>(x, p_xh, HID);
    split_tiled<<<(N_QKV * HID) / 2048, 256>>>(w_qkv, p_wqh, HID);
    split_tiled<<<(HID * QKV_) / 2048, 256>>>(w_o, p_woh, QKV_);

    // 1) QKV projection — emits Q (scaled), K, V directly as fp16 tiles
    {
        dim3 grid(N_QKV / 128, M_TOK / 128);
        gemm_f16<<<grid, 256, GEMM_SMEM>>>(p_xh, p_wqh, b_qkv, nullptr,
                                           p_qh, p_kh, p_vh,
                                           M_TOK, N_QKV, HID, 1);
    }
    // 2) attention (fully fp16 in/out)
    {
        dim3 grid(S_ / 128, B_ * H_);
        attn_tc<<<grid, 256, ATT_SMEM>>>(p_qh, p_kh, p_vh, p_ath);
    }
    // 3) output projection (fp32 out)
    {
        dim3 grid(QKV_ / 128, M_TOK / 128);
        gemm_f16<<<grid, 256, GEMM_SMEM>>>(p_ath, p_woh, b_o, out,
                                           nullptr, nullptr, nullptr,
                                           M_TOK, QKV_, HID, 0);
    }
}